// round 2
// baseline (speedup 1.0000x reference)
#include <cuda_runtime.h>
#include <cuda_bf16.h>
#include <cstdint>

// ---------------------------------------------------------------------------
// GCNEncoder: out = GCNConv2( relu( GCNConv1(x) ) )
//   GCNConv(x) = segment_sum_dst( (x@W)[src] * dinv[s]*dinv[d] ) + (x@W)*dinv^2 + b
// Prescale trick: h_s = (x@W)*dinv  =>  agg[d] = sum_e h_s[src];
//   out = dinv[d]*(agg[d] + h_s[d]) + b
// Dims: 128 -> 128 -> 64.  N = 100000, E = 1.6M.
// edge_index dtype is sniffed at runtime (JAX silently downgrades int64->int32).
// ---------------------------------------------------------------------------

#define NMAX 100000
#define EMAX 1600000
#define D0 128
#define D1 128
#define D2 64

__device__ float g_dinv[NMAX];
__device__ float g_h[(size_t)NMAX * D1];    // h_s (scaled transform output)
__device__ float g_agg[(size_t)NMAX * D1];  // layer-1 result / layer-2 input
__device__ int   g_src[EMAX];
__device__ int   g_dst[EMAX];
__device__ int   g_idx64;                   // 1 if edge_index is int64

// ---------------------------------------------------------------------------
// dtype probe: int64 data (values < 2^31) has all-zero high words
// ---------------------------------------------------------------------------
__global__ void probe_kernel(const int* __restrict__ w, int nwords) {
    if (threadIdx.x == 0 && blockIdx.x == 0) {
        int limit = nwords < 2048 ? nwords : 2048;
        int acc = 0;
        for (int i = 1; i < limit; i += 2) acc |= w[i];
        g_idx64 = (acc == 0) ? 1 : 0;
    }
}

__global__ void decode_kernel(const int* __restrict__ w, int E, int n) {
    int e = blockIdx.x * blockDim.x + threadIdx.x;
    if (e >= E) return;
    int s, d;
    if (g_idx64) {
        s = w[2 * (size_t)e];
        d = w[2 * ((size_t)E + e)];
    } else {
        s = w[e];
        d = w[(size_t)E + e];
    }
    // bounds-guard: clamp bad indices to a benign self-edge at node 0 weight path
    if ((unsigned)s >= (unsigned)n) s = 0;
    if ((unsigned)d >= (unsigned)n) d = 0;
    g_src[e] = s;
    g_dst[e] = d;
}

// ---------------------------------------------------------------------------
// degree + normalization
// ---------------------------------------------------------------------------
__global__ void fill_kernel(float* p, int n, float v) {
    int i = blockIdx.x * blockDim.x + threadIdx.x;
    if (i < n) p[i] = v;
}

__global__ void deg_kernel(const int* __restrict__ dst, float* deg, int E) {
    int e = blockIdx.x * blockDim.x + threadIdx.x;
    if (e < E) atomicAdd(&deg[dst[e]], 1.0f);
}

__global__ void rsqrt_kernel(float* p, int n) {
    int i = blockIdx.x * blockDim.x + threadIdx.x;
    if (i < n) {
        float v = p[i];
        p[i] = (v > 0.f) ? rsqrtf(v) : 0.f;
    }
}

// ---------------------------------------------------------------------------
// SGEMM with dinv-scaled epilogue: C[r,:] = dinv[r] * (A[r,:] @ W)
// BM=128, BK=8, 256 threads, 8 x TN microtile per thread.
// ---------------------------------------------------------------------------
template <int IN, int OUT, int TN>
__global__ void __launch_bounds__(256) sgemm_kernel(
    const float* __restrict__ A, const float* __restrict__ W,
    float* __restrict__ C, const float* __restrict__ dinv, int n)
{
    constexpr int BM = 128;
    constexpr int BK = 8;
    constexpr int NTX = OUT / TN;  // 16

    __shared__ float As[BK][BM];
    __shared__ float Bs[BK][OUT];

    const int tid = threadIdx.x;
    const int tx = tid % NTX;
    const int ty = tid / NTX;
    const int row0 = blockIdx.x * BM;

    float acc[8][TN];
#pragma unroll
    for (int i = 0; i < 8; i++)
#pragma unroll
        for (int j = 0; j < TN; j++) acc[i][j] = 0.f;

    const int ar = tid >> 1;
    const int ac = (tid & 1) << 2;

    for (int k0 = 0; k0 < IN; k0 += BK) {
        float4 av = make_float4(0.f, 0.f, 0.f, 0.f);
        if (row0 + ar < n)
            av = *(const float4*)&A[(size_t)(row0 + ar) * IN + k0 + ac];
        As[ac + 0][ar] = av.x;
        As[ac + 1][ar] = av.y;
        As[ac + 2][ar] = av.z;
        As[ac + 3][ar] = av.w;

#pragma unroll
        for (int i = tid; i < BK * OUT; i += 256)
            Bs[i / OUT][i % OUT] = W[(size_t)(k0 + i / OUT) * OUT + (i % OUT)];

        __syncthreads();

#pragma unroll
        for (int k = 0; k < BK; k++) {
            float a[8], b[TN];
            *(float4*)&a[0] = *(const float4*)&As[k][ty * 8];
            *(float4*)&a[4] = *(const float4*)&As[k][ty * 8 + 4];
#pragma unroll
            for (int j = 0; j < TN; j += 4)
                *(float4*)&b[j] = *(const float4*)&Bs[k][tx * TN + j];
#pragma unroll
            for (int i = 0; i < 8; i++)
#pragma unroll
                for (int j = 0; j < TN; j++) acc[i][j] += a[i] * b[j];
        }
        __syncthreads();
    }

#pragma unroll
    for (int i = 0; i < 8; i++) {
        int row = row0 + ty * 8 + i;
        if (row < n) {
            float sc = dinv[row];
#pragma unroll
            for (int j = 0; j < TN; j += 4) {
                float4 v = make_float4(acc[i][j] * sc, acc[i][j + 1] * sc,
                                       acc[i][j + 2] * sc, acc[i][j + 3] * sc);
                *(float4*)&C[(size_t)row * OUT + tx * TN + j] = v;
            }
        }
    }
}

// ---------------------------------------------------------------------------
// Edge scatter: agg[dst] += h_s[src]   (pure gather + vector red)
// DIM/4 threads per edge; fully coalesced float4 accesses.
// ---------------------------------------------------------------------------
__device__ __forceinline__ void red_add_v4(float* addr, float4 v) {
    asm volatile("red.global.add.v4.f32 [%0], {%1, %2, %3, %4};"
                 :: "l"(addr), "f"(v.x), "f"(v.y), "f"(v.z), "f"(v.w)
                 : "memory");
}

template <int DIM>
__global__ void __launch_bounds__(256) scatter_kernel(
    const int* __restrict__ src, const int* __restrict__ dst,
    const float* __restrict__ h, float* __restrict__ agg, int E)
{
    constexpr int L = DIM / 4;
    long long t = (long long)blockIdx.x * blockDim.x + threadIdx.x;
    long long e = t / L;
    int l = (int)(t % L);
    if (e >= E) return;

    int s = src[e];
    int d = dst[e];
    float4 v = *(const float4*)&h[(size_t)s * DIM + l * 4];
    red_add_v4(&agg[(size_t)d * DIM + l * 4], v);
}

// ---------------------------------------------------------------------------
// Finish: res = f( dinv[node]*(agg + h_s) + b )
// ---------------------------------------------------------------------------
template <int DIM, bool RELU>
__global__ void __launch_bounds__(256) finish_kernel(
    const float* __restrict__ agg, const float* __restrict__ h,
    float* __restrict__ res, const float* __restrict__ dinv,
    const float* __restrict__ bias, int n)
{
    constexpr int L = DIM / 4;
    long long t = (long long)blockIdx.x * blockDim.x + threadIdx.x;
    if (t >= (long long)n * L) return;
    int node = (int)(t / L);
    int c = (int)(t % L);

    float di = dinv[node];
    float4 a = *(const float4*)&agg[(size_t)node * DIM + c * 4];
    float4 hv = *(const float4*)&h[(size_t)node * DIM + c * 4];
    float4 b = *(const float4*)&bias[c * 4];

    float4 r;
    r.x = di * (a.x + hv.x) + b.x;
    r.y = di * (a.y + hv.y) + b.y;
    r.z = di * (a.z + hv.z) + b.z;
    r.w = di * (a.w + hv.w) + b.w;
    if (RELU) {
        r.x = fmaxf(r.x, 0.f);
        r.y = fmaxf(r.y, 0.f);
        r.z = fmaxf(r.z, 0.f);
        r.w = fmaxf(r.w, 0.f);
    }
    *(float4*)&res[(size_t)node * DIM + c * 4] = r;
}

// ---------------------------------------------------------------------------
// launch
// ---------------------------------------------------------------------------
static inline int cdiv(long long a, long long b) { return (int)((a + b - 1) / b); }

extern "C" void kernel_launch(void* const* d_in, const int* in_sizes, int n_in,
                              void* d_out, int out_size)
{
    const float* x   = (const float*)d_in[0];
    const int*   eiw = (const int*)d_in[1];   // raw words; dtype sniffed on device
    const float* W1  = (const float*)d_in[2];
    const float* b1  = (const float*)d_in[3];
    const float* W2  = (const float*)d_in[4];
    const float* b2  = (const float*)d_in[5];
    float*       out = (float*)d_out;

    const int n = in_sizes[0] / D0;
    int E = in_sizes[1] / 2;
    if (E > EMAX) E = EMAX;

    float *dinv, *h, *agg;
    int *srcp, *dstp;
    cudaGetSymbolAddress((void**)&dinv, g_dinv);
    cudaGetSymbolAddress((void**)&h,    g_h);
    cudaGetSymbolAddress((void**)&agg,  g_agg);
    cudaGetSymbolAddress((void**)&srcp, g_src);
    cudaGetSymbolAddress((void**)&dstp, g_dst);

    // --- decode edge indices (dtype-robust) ---
    probe_kernel<<<1, 32>>>(eiw, in_sizes[1]);
    decode_kernel<<<cdiv(E, 256), 256>>>(eiw, E, n);

    // --- degree + normalization ---
    fill_kernel<<<cdiv(n, 256), 256>>>(dinv, n, 1.0f);  // self-loop contributes 1
    deg_kernel<<<cdiv(E, 256), 256>>>(dstp, dinv, E);
    rsqrt_kernel<<<cdiv(n, 256), 256>>>(dinv, n);

    // --- layer 1 ---
    sgemm_kernel<D0, D1, 8><<<cdiv(n, 128), 256>>>(x, W1, h, dinv, n);
    cudaMemsetAsync(agg, 0, (size_t)n * D1 * sizeof(float));
    scatter_kernel<D1><<<cdiv((long long)E * (D1 / 4), 256), 256>>>(srcp, dstp, h, agg, E);
    finish_kernel<D1, true><<<cdiv((long long)n * (D1 / 4), 256), 256>>>(agg, h, agg, dinv, b1, n);

    // --- layer 2 ---
    sgemm_kernel<D1, D2, 4><<<cdiv(n, 128), 256>>>(agg, W2, h, dinv, n);
    cudaMemsetAsync(out, 0, (size_t)n * D2 * sizeof(float));
    scatter_kernel<D2><<<cdiv((long long)E * (D2 / 4), 256), 256>>>(srcp, dstp, h, out, E);
    finish_kernel<D2, false><<<cdiv((long long)n * (D2 / 4), 256), 256>>>(out, h, out, dinv, b2, n);
}

// round 5
// speedup vs baseline: 1.0583x; 1.0583x over previous
#include <cuda_runtime.h>
#include <cuda_bf16.h>
#include <cstdint>

// ---------------------------------------------------------------------------
// GCNEncoder: out = GCNConv2( relu( GCNConv1(x) ) )
// Prescale: h_s = (x@W)*dinv ; agg[d] = sum_e h_s[src] ; out = dinv*(agg+h_s)+b
// GEMMs: tcgen05 bf16 hi/lo split when compiled with sm_103a features,
//        tiled FFMA fallback otherwise (virtual compute_103 pass).
// ---------------------------------------------------------------------------

#define NMAX 100000
#define EMAX 1600000
#define D0 128
#define D1 128
#define D2 64

#if defined(__CUDA_ARCH_FEAT_SM103_ALL) || defined(__CUDA_ARCH_FEAT_SM100_ALL) || \
    (defined(__CUDA_ARCH_SPECIFIC__) && (__CUDA_ARCH__ >= 1000))
#define HAS_TCGEN05 1
#else
#define HAS_TCGEN05 0
#endif

__device__ float g_dinv[NMAX];
__device__ float g_h[(size_t)NMAX * D1];
__device__ float g_agg[(size_t)NMAX * D1];
__device__ int   g_src[EMAX];
__device__ int   g_dst[EMAX];
__device__ int   g_idx64;

// ---------------------------------------------------------------------------
// PTX helpers
// ---------------------------------------------------------------------------
__device__ __forceinline__ uint32_t smem_u32(const void* p) {
    uint32_t a;
    asm("{ .reg .u64 t; cvta.to.shared.u64 t, %1; cvt.u32.u64 %0, t; }"
        : "=r"(a) : "l"(p));
    return a;
}

#if HAS_TCGEN05
__device__ __forceinline__ uint32_t elect1() {
    uint32_t p;
    asm volatile("{ .reg .pred p; elect.sync _|p, 0xFFFFFFFF; selp.b32 %0,1,0,p; }"
                 : "=r"(p));
    return p;
}

#define TC_ALLOC(smem_addr, ncols) \
    asm volatile("tcgen05.alloc.cta_group::1.sync.aligned.shared::cta.b32 [%0], %1;" \
                 :: "r"(smem_addr), "r"(ncols) : "memory")
#define TC_DEALLOC(tmem, ncols) \
    asm volatile("tcgen05.dealloc.cta_group::1.sync.aligned.b32 %0, %1;" \
                 :: "r"(tmem), "r"(ncols))
#define TC_COMMIT(mbar) \
    asm volatile("tcgen05.commit.cta_group::1.mbarrier::arrive::one.shared::cluster.b64 [%0];" \
                 :: "r"(mbar) : "memory")
#define TC_WAIT_LD() asm volatile("tcgen05.wait::ld.sync.aligned;" ::: "memory")
#define TC_FENCE_AFTER() asm volatile("tcgen05.fence::after_thread_sync;" ::: "memory")
#define MBAR_INIT(mbar, cnt) \
    asm volatile("mbarrier.init.shared.b64 [%0], %1;" :: "r"(mbar), "r"(cnt) : "memory")

#define MBAR_WAIT(mbar, ph) do {                                              \
    uint32_t _done;                                                           \
    asm volatile("{\n\t.reg .pred p;\n\t"                                     \
        "mbarrier.try_wait.parity.acquire.cta.shared::cta.b64 p, [%1], %2;\n\t" \
        "selp.b32 %0,1,0,p;\n\t}"                                             \
        : "=r"(_done) : "r"(mbar), "r"(ph) : "memory");                       \
    if (!_done) {                                                             \
        asm volatile("{\n\t.reg .pred P1;\n\t"                                \
            "W1_%=:\n\t"                                                      \
            "mbarrier.try_wait.parity.acquire.cta.shared::cta.b64 P1, [%0], %1, 0x989680;\n\t" \
            "@P1 bra.uni W2_%=;\n\tbra.uni W1_%=;\n\tW2_%=:\n\t}"             \
            :: "r"(mbar), "r"(ph) : "memory");                                \
    }                                                                         \
} while (0)

#define TC_LD_X32(r, tmem)                                                    \
    asm volatile("tcgen05.ld.sync.aligned.32x32b.x32.b32 "                    \
        "{%0, %1, %2, %3, %4, %5, %6, %7, "                                   \
        " %8, %9, %10, %11, %12, %13, %14, %15, "                             \
        " %16, %17, %18, %19, %20, %21, %22, %23, "                           \
        " %24, %25, %26, %27, %28, %29, %30, %31}, [%32];"                    \
        : "=r"((r)[0]),  "=r"((r)[1]),  "=r"((r)[2]),  "=r"((r)[3]),          \
          "=r"((r)[4]),  "=r"((r)[5]),  "=r"((r)[6]),  "=r"((r)[7]),          \
          "=r"((r)[8]),  "=r"((r)[9]),  "=r"((r)[10]), "=r"((r)[11]),         \
          "=r"((r)[12]), "=r"((r)[13]), "=r"((r)[14]), "=r"((r)[15]),         \
          "=r"((r)[16]), "=r"((r)[17]), "=r"((r)[18]), "=r"((r)[19]),         \
          "=r"((r)[20]), "=r"((r)[21]), "=r"((r)[22]), "=r"((r)[23]),         \
          "=r"((r)[24]), "=r"((r)[25]), "=r"((r)[26]), "=r"((r)[27]),         \
          "=r"((r)[28]), "=r"((r)[29]), "=r"((r)[30]), "=r"((r)[31])          \
        : "r"(tmem))

__device__ __forceinline__ void mma_ss_f16(uint32_t d, uint64_t a, uint64_t b,
                                           uint32_t idesc, bool acc) {
    uint32_t e = acc ? 1u : 0u;
    asm volatile(
        "{\n\t.reg .pred p;\n\tsetp.ne.u32 p, %4, 0;\n\t"
        "tcgen05.mma.cta_group::1.kind::f16 [%0], %1, %2, %3, {%5,%5,%5,%5}, p;\n\t}"
        :: "r"(d), "l"(a), "l"(b), "r"(idesc), "r"(e), "r"(0u)
        : "memory");
}
#endif  // HAS_TCGEN05

// SW128 blocked-atom offset: atom = 8 rows x 64 bf16 (1024B), col-major atoms.
template <int ROWS>
__device__ __forceinline__ uint32_t sw_off(int r, int c) {
    uint32_t atom = (uint32_t)(r >> 3) + (uint32_t)(c >> 6) * (ROWS >> 3);
    uint32_t off = atom * 1024 + (r & 7) * 128 + (c & 63) * 2;
    return off ^ ((off >> 3) & 0x70);
}

__device__ __forceinline__ void split4(float4 v, unsigned long long& hi,
                                       unsigned long long& lo) {
    __nv_bfloat16 h0 = __float2bfloat16(v.x), h1 = __float2bfloat16(v.y);
    __nv_bfloat16 h2 = __float2bfloat16(v.z), h3 = __float2bfloat16(v.w);
    __nv_bfloat16 l0 = __float2bfloat16(v.x - __bfloat162float(h0));
    __nv_bfloat16 l1 = __float2bfloat16(v.y - __bfloat162float(h1));
    __nv_bfloat16 l2 = __float2bfloat16(v.z - __bfloat162float(h2));
    __nv_bfloat16 l3 = __float2bfloat16(v.w - __bfloat162float(h3));
    hi = (unsigned long long)__bfloat16_as_ushort(h0)
       | ((unsigned long long)__bfloat16_as_ushort(h1) << 16)
       | ((unsigned long long)__bfloat16_as_ushort(h2) << 32)
       | ((unsigned long long)__bfloat16_as_ushort(h3) << 48);
    lo = (unsigned long long)__bfloat16_as_ushort(l0)
       | ((unsigned long long)__bfloat16_as_ushort(l1) << 16)
       | ((unsigned long long)__bfloat16_as_ushort(l2) << 32)
       | ((unsigned long long)__bfloat16_as_ushort(l3) << 48);
}

// ---------------------------------------------------------------------------
// GEMM: C[r,:] = dinv[r] * (A[r,:] @ W),  A: [n,128], W: [128,OUT]
// One CTA = 128 rows.  tcgen05 path (sm_103a) or tiled FFMA fallback.
// ---------------------------------------------------------------------------
template <int OUT>
__global__ void __launch_bounds__(128) tc_gemm(
    const float* __restrict__ A, const float* __restrict__ W,
    float* __restrict__ C, const float* __restrict__ dinv, int n)
{
    extern __shared__ char smem[];
    constexpr int K = 128;
    const int tid = threadIdx.x;
    const int row0 = blockIdx.x * 128;

#if HAS_TCGEN05
    constexpr uint32_t A_HI = 1024;
    constexpr uint32_t A_LO = A_HI + 128 * 256;
    constexpr uint32_t B_HI = A_LO + 128 * 256;
    constexpr uint32_t B_LO = B_HI + OUT * 256;

    const uint32_t sb = smem_u32(smem);
    const int wid = tid >> 5, lane = tid & 31;

    if (wid == 0) TC_ALLOC(sb + 0, 128);
    __syncthreads();
    uint32_t tmem;
    asm volatile("ld.shared.b32 %0, [%1];" : "=r"(tmem) : "r"(sb + 0));

    // --- A tile: thread tid handles row tid ---
    {
        int r = row0 + tid;
        if (r < n) {
            const float4* src = (const float4*)&A[(size_t)r * K];
#pragma unroll
            for (int c = 0; c < K; c += 4) {
                unsigned long long hi, lo;
                split4(src[c >> 2], hi, lo);
                uint32_t o = sw_off<128>(tid, c);
                *(unsigned long long*)(smem + A_HI + o) = hi;
                *(unsigned long long*)(smem + A_LO + o) = lo;
            }
        } else {
#pragma unroll
            for (int c = 0; c < K; c += 4) {
                uint32_t o = sw_off<128>(tid, c);
                *(unsigned long long*)(smem + A_HI + o) = 0ull;
                *(unsigned long long*)(smem + A_LO + o) = 0ull;
            }
        }
    }

    // --- B tile: B[nrow][k] = W[k][nrow] (transpose load, hi/lo split) ---
    {
        int br, k0, kcnt;
        if (OUT == 128) { br = tid; k0 = 0; kcnt = K; }
        else { br = tid & (OUT - 1); k0 = (tid / OUT) * (K / (128 / OUT)); kcnt = K / (128 / OUT); }
#pragma unroll 4
        for (int k = k0; k < k0 + kcnt; k += 4) {
            float4 v = make_float4(W[(size_t)(k + 0) * OUT + br],
                                   W[(size_t)(k + 1) * OUT + br],
                                   W[(size_t)(k + 2) * OUT + br],
                                   W[(size_t)(k + 3) * OUT + br]);
            unsigned long long hi, lo;
            split4(v, hi, lo);
            uint32_t o = sw_off<OUT>(br, k);
            *(unsigned long long*)(smem + B_HI + o) = hi;
            *(unsigned long long*)(smem + B_LO + o) = lo;
        }
    }
    asm volatile("fence.proxy.async.shared::cta;" ::: "memory");
    __syncthreads();

    if (tid == 0) MBAR_INIT(sb + 8, 1);
    __syncthreads();

    if (wid == 0) {
        if (elect1()) {
            const uint64_t DB = (2ull << 61) | (1ull << 46) | (64ull << 32) | (1ull << 16);
            uint64_t dAhi = DB | (((sb + A_HI) >> 4) & 0x3FFF);
            uint64_t dAlo = DB | (((sb + A_LO) >> 4) & 0x3FFF);
            uint64_t dBhi = DB | (((sb + B_HI) >> 4) & 0x3FFF);
            uint64_t dBlo = DB | (((sb + B_LO) >> 4) & 0x3FFF);
            constexpr uint32_t idesc =
                (1u << 4) | (1u << 7) | (1u << 10) | ((OUT / 8) << 17) | (8u << 24);
            bool first = true;
#pragma unroll
            for (int s = 0; s < 8; s++) {
                uint64_t ao = (s < 4) ? (uint64_t)(s * 2) : (uint64_t)(1024 + (s - 4) * 2);
                uint64_t bo = (s < 4) ? (uint64_t)(s * 2) : (uint64_t)(OUT * 8 + (s - 4) * 2);
                mma_ss_f16(tmem, dAhi + ao, dBhi + bo, idesc, !first);
                first = false;
                mma_ss_f16(tmem, dAhi + ao, dBlo + bo, idesc, true);
                mma_ss_f16(tmem, dAlo + ao, dBhi + bo, idesc, true);
            }
            TC_COMMIT(sb + 8);
        }
    }

    MBAR_WAIT(sb + 8, 0);
    TC_FENCE_AFTER();

    // --- epilogue: warp w owns rows [row0+32w, +32) ---
    {
        int r = row0 + wid * 32 + lane;
        float sc = (r < n) ? dinv[r] : 0.f;
#pragma unroll
        for (int ch = 0; ch < OUT; ch += 32) {
            uint32_t rg[32];
            TC_LD_X32(rg, tmem + ch);
            TC_WAIT_LD();
            if (r < n) {
#pragma unroll
                for (int j = 0; j < 32; j += 4) {
                    float4 v = make_float4(__uint_as_float(rg[j + 0]) * sc,
                                           __uint_as_float(rg[j + 1]) * sc,
                                           __uint_as_float(rg[j + 2]) * sc,
                                           __uint_as_float(rg[j + 3]) * sc);
                    *(float4*)&C[(size_t)r * OUT + ch + j] = v;
                }
            }
        }
    }

    __syncthreads();
    if (wid == 0) {
        if (elect1())
            asm volatile("mbarrier.inval.shared.b64 [%0];" :: "r"(sb + 8) : "memory");
        TC_DEALLOC(tmem, 128);
    }

#else  // ------------------- FFMA fallback (virtual-arch build) -------------
    // 128 threads; two 64-row halves; BK=8 tiles; NTX*8 cols x RPT rows/thread.
    constexpr int NTX = OUT / 8;          // 16 (OUT=128) or 8 (OUT=64)
    constexpr int NTY = 128 / NTX;        // 8 or 16
    constexpr int RPT = 64 / NTY;         // 8 or 4
    float* As = (float*)smem;             // [8][64]  As[k][r]
    float* Bs = (float*)(smem + 8 * 64 * 4);  // [8][OUT]

    const int tx = tid % NTX;
    const int ty = tid / NTX;

    for (int half = 0; half < 2; half++) {
        const int rbase = row0 + half * 64;
        float acc[RPT][8];
#pragma unroll
        for (int i = 0; i < RPT; i++)
#pragma unroll
            for (int j = 0; j < 8; j++) acc[i][j] = 0.f;

        for (int k0 = 0; k0 < K; k0 += 8) {
            int ar = tid >> 1, ac = (tid & 1) << 2;
            float4 av = make_float4(0.f, 0.f, 0.f, 0.f);
            if (rbase + ar < n)
                av = *(const float4*)&A[(size_t)(rbase + ar) * K + k0 + ac];
            As[(ac + 0) * 64 + ar] = av.x;
            As[(ac + 1) * 64 + ar] = av.y;
            As[(ac + 2) * 64 + ar] = av.z;
            As[(ac + 3) * 64 + ar] = av.w;
#pragma unroll
            for (int i = tid; i < 8 * OUT; i += 128)
                Bs[i] = W[(size_t)(k0 + i / OUT) * OUT + (i % OUT)];
            __syncthreads();
#pragma unroll
            for (int k = 0; k < 8; k++) {
                float a[RPT], b[8];
#pragma unroll
                for (int i = 0; i < RPT; i++) a[i] = As[k * 64 + ty * RPT + i];
                *(float4*)&b[0] = *(float4*)&Bs[k * OUT + tx * 8];
                *(float4*)&b[4] = *(float4*)&Bs[k * OUT + tx * 8 + 4];
#pragma unroll
                for (int i = 0; i < RPT; i++)
#pragma unroll
                    for (int j = 0; j < 8; j++) acc[i][j] += a[i] * b[j];
            }
            __syncthreads();
        }

#pragma unroll
        for (int i = 0; i < RPT; i++) {
            int r = rbase + ty * RPT + i;
            if (r < n) {
                float sc = dinv[r];
                float4 v0 = make_float4(acc[i][0] * sc, acc[i][1] * sc,
                                        acc[i][2] * sc, acc[i][3] * sc);
                float4 v1 = make_float4(acc[i][4] * sc, acc[i][5] * sc,
                                        acc[i][6] * sc, acc[i][7] * sc);
                *(float4*)&C[(size_t)r * OUT + tx * 8] = v0;
                *(float4*)&C[(size_t)r * OUT + tx * 8 + 4] = v1;
            }
        }
        __syncthreads();
    }
#endif
}

// ---------------------------------------------------------------------------
// edge decode / degree / norm
// ---------------------------------------------------------------------------
__global__ void probe_kernel(const int* __restrict__ w, int nwords) {
    if (threadIdx.x == 0 && blockIdx.x == 0) {
        int limit = nwords < 2048 ? nwords : 2048;
        int acc = 0;
        for (int i = 1; i < limit; i += 2) acc |= w[i];
        g_idx64 = (acc == 0) ? 1 : 0;
    }
}

__global__ void decode_kernel(const int* __restrict__ w, int E, int n) {
    int e = blockIdx.x * blockDim.x + threadIdx.x;
    if (e >= E) return;
    int s, d;
    if (g_idx64) {
        s = w[2 * (size_t)e];
        d = w[2 * ((size_t)E + e)];
    } else {
        s = w[e];
        d = w[(size_t)E + e];
    }
    if ((unsigned)s >= (unsigned)n) s = 0;
    if ((unsigned)d >= (unsigned)n) d = 0;
    g_src[e] = s;
    g_dst[e] = d;
}

__global__ void fill_kernel(float* p, int n, float v) {
    int i = blockIdx.x * blockDim.x + threadIdx.x;
    if (i < n) p[i] = v;
}

__global__ void deg_kernel(const int* __restrict__ dst, float* deg, int E) {
    int e = blockIdx.x * blockDim.x + threadIdx.x;
    if (e < E) atomicAdd(&deg[dst[e]], 1.0f);
}

__global__ void rsqrt_kernel(float* p, int n) {
    int i = blockIdx.x * blockDim.x + threadIdx.x;
    if (i < n) {
        float v = p[i];
        p[i] = (v > 0.f) ? rsqrtf(v) : 0.f;
    }
}

// ---------------------------------------------------------------------------
// edge scatter + finish
// ---------------------------------------------------------------------------
__device__ __forceinline__ void red_add_v4(float* addr, float4 v) {
    asm volatile("red.global.add.v4.f32 [%0], {%1, %2, %3, %4};"
                 :: "l"(addr), "f"(v.x), "f"(v.y), "f"(v.z), "f"(v.w)
                 : "memory");
}

template <int DIM>
__global__ void __launch_bounds__(256) scatter_kernel(
    const int* __restrict__ src, const int* __restrict__ dst,
    const float* __restrict__ h, float* __restrict__ agg, int E)
{
    constexpr int L = DIM / 4;
    long long t = (long long)blockIdx.x * blockDim.x + threadIdx.x;
    long long e = t / L;
    int l = (int)(t % L);
    if (e >= E) return;
    int s = src[e];
    int d = dst[e];
    float4 v = *(const float4*)&h[(size_t)s * DIM + l * 4];
    red_add_v4(&agg[(size_t)d * DIM + l * 4], v);
}

template <int DIM, bool RELU>
__global__ void __launch_bounds__(256) finish_kernel(
    const float* __restrict__ agg, const float* __restrict__ h,
    float* __restrict__ res, const float* __restrict__ dinv,
    const float* __restrict__ bias, int n)
{
    constexpr int L = DIM / 4;
    long long t = (long long)blockIdx.x * blockDim.x + threadIdx.x;
    if (t >= (long long)n * L) return;
    int node = (int)(t / L);
    int c = (int)(t % L);

    float di = dinv[node];
    float4 a = *(const float4*)&agg[(size_t)node * DIM + c * 4];
    float4 hv = *(const float4*)&h[(size_t)node * DIM + c * 4];
    float4 b = *(const float4*)&bias[c * 4];

    float4 r;
    r.x = di * (a.x + hv.x) + b.x;
    r.y = di * (a.y + hv.y) + b.y;
    r.z = di * (a.z + hv.z) + b.z;
    r.w = di * (a.w + hv.w) + b.w;
    if (RELU) {
        r.x = fmaxf(r.x, 0.f);
        r.y = fmaxf(r.y, 0.f);
        r.z = fmaxf(r.z, 0.f);
        r.w = fmaxf(r.w, 0.f);
    }
    *(float4*)&res[(size_t)node * DIM + c * 4] = r;
}

// ---------------------------------------------------------------------------
// launch
// ---------------------------------------------------------------------------
static inline int cdiv(long long a, long long b) { return (int)((a + b - 1) / b); }

extern "C" void kernel_launch(void* const* d_in, const int* in_sizes, int n_in,
                              void* d_out, int out_size)
{
    const float* x   = (const float*)d_in[0];
    const int*   eiw = (const int*)d_in[1];
    const float* W1  = (const float*)d_in[2];
    const float* b1  = (const float*)d_in[3];
    const float* W2  = (const float*)d_in[4];
    const float* b2  = (const float*)d_in[5];
    float*       out = (float*)d_out;

    const int n = in_sizes[0] / D0;
    int E = in_sizes[1] / 2;
    if (E > EMAX) E = EMAX;

    float *dinv, *h, *agg;
    int *srcp, *dstp;
    cudaGetSymbolAddress((void**)&dinv, g_dinv);
    cudaGetSymbolAddress((void**)&h,    g_h);
    cudaGetSymbolAddress((void**)&agg,  g_agg);
    cudaGetSymbolAddress((void**)&srcp, g_src);
    cudaGetSymbolAddress((void**)&dstp, g_dst);

    constexpr int SMEM1 = 1024 + 2 * 128 * 256 + 2 * 128 * 256;  // 132096
    constexpr int SMEM2 = 1024 + 2 * 128 * 256 + 2 * 64 * 256;   //  99328
    cudaFuncSetAttribute(tc_gemm<128>, cudaFuncAttributeMaxDynamicSharedMemorySize, SMEM1);
    cudaFuncSetAttribute(tc_gemm<64>,  cudaFuncAttributeMaxDynamicSharedMemorySize, SMEM2);

    // --- decode edge indices (dtype-robust) ---
    probe_kernel<<<1, 32>>>(eiw, in_sizes[1]);
    decode_kernel<<<cdiv(E, 256), 256>>>(eiw, E, n);

    // --- degree + normalization ---
    fill_kernel<<<cdiv(n, 256), 256>>>(dinv, n, 1.0f);
    deg_kernel<<<cdiv(E, 256), 256>>>(dstp, dinv, E);
    rsqrt_kernel<<<cdiv(n, 256), 256>>>(dinv, n);

    // --- layer 1 ---
    tc_gemm<D1><<<cdiv(n, 128), 128, SMEM1>>>(x, W1, h, dinv, n);
    cudaMemsetAsync(agg, 0, (size_t)n * D1 * sizeof(float));
    scatter_kernel<D1><<<cdiv((long long)E * (D1 / 4), 256), 256>>>(srcp, dstp, h, agg, E);
    finish_kernel<D1, true><<<cdiv((long long)n * (D1 / 4), 256), 256>>>(agg, h, agg, dinv, b1, n);

    // --- layer 2 ---
    tc_gemm<D2><<<cdiv(n, 128), 128, SMEM2>>>(agg, W2, h, dinv, n);
    cudaMemsetAsync(out, 0, (size_t)n * D2 * sizeof(float));
    scatter_kernel<D2><<<cdiv((long long)E * (D2 / 4), 256), 256>>>(srcp, dstp, h, out, E);
    finish_kernel<D2, false><<<cdiv((long long)n * (D2 / 4), 256), 256>>>(out, h, out, dinv, b2, n);
}

// round 6
// speedup vs baseline: 1.7347x; 1.6391x over previous
#include <cuda_runtime.h>
#include <cuda_bf16.h>
#include <cstdint>

// ---------------------------------------------------------------------------
// GCNEncoder: out = GCNConv2( relu( GCNConv1(x) ) )
// Prescale: h_s = (x@W)*dinv ; agg[d] = sum_in h_s[src] ; out = dinv*(agg+h_s)+b
// Edges counting-sorted by dst (CSR) -> atomic-free warp-per-node gather.
// GEMMs: tcgen05 bf16 hi/lo split (sm_103a) / FFMA fallback (compute_103).
// ---------------------------------------------------------------------------

#define NMAX 100000
#define EMAX 1600000
#define D0 128
#define D1 128
#define D2 64
#define SCAN_B 1024

#if defined(__CUDA_ARCH_FEAT_SM103_ALL) || defined(__CUDA_ARCH_FEAT_SM100_ALL) || \
    (defined(__CUDA_ARCH_SPECIFIC__) && (__CUDA_ARCH__ >= 1000))
#define HAS_TCGEN05 1
#else
#define HAS_TCGEN05 0
#endif

__device__ float g_dinv[NMAX];
__device__ float g_h[(size_t)NMAX * D1];
__device__ float g_agg[(size_t)NMAX * D1];
__device__ int   g_src[EMAX];
__device__ int   g_dst[EMAX];
__device__ int   g_sorted[EMAX];
__device__ int   g_cnt[NMAX];
__device__ int   g_rowptr[NMAX + 1];
__device__ int   g_cursor[NMAX];
__device__ int   g_bsum[128];
__device__ int   g_bpre[128];
__device__ int   g_idx64;

// ---------------------------------------------------------------------------
// PTX helpers
// ---------------------------------------------------------------------------
__device__ __forceinline__ uint32_t smem_u32(const void* p) {
    uint32_t a;
    asm("{ .reg .u64 t; cvta.to.shared.u64 t, %1; cvt.u32.u64 %0, t; }"
        : "=r"(a) : "l"(p));
    return a;
}

#if HAS_TCGEN05
__device__ __forceinline__ uint32_t elect1() {
    uint32_t p;
    asm volatile("{ .reg .pred p; elect.sync _|p, 0xFFFFFFFF; selp.b32 %0,1,0,p; }"
                 : "=r"(p));
    return p;
}

#define TC_ALLOC(smem_addr, ncols) \
    asm volatile("tcgen05.alloc.cta_group::1.sync.aligned.shared::cta.b32 [%0], %1;" \
                 :: "r"(smem_addr), "r"(ncols) : "memory")
#define TC_DEALLOC(tmem, ncols) \
    asm volatile("tcgen05.dealloc.cta_group::1.sync.aligned.b32 %0, %1;" \
                 :: "r"(tmem), "r"(ncols))
#define TC_COMMIT(mbar) \
    asm volatile("tcgen05.commit.cta_group::1.mbarrier::arrive::one.shared::cluster.b64 [%0];" \
                 :: "r"(mbar) : "memory")
#define TC_WAIT_LD() asm volatile("tcgen05.wait::ld.sync.aligned;" ::: "memory")
#define TC_FENCE_AFTER() asm volatile("tcgen05.fence::after_thread_sync;" ::: "memory")
#define MBAR_INIT(mbar, cnt) \
    asm volatile("mbarrier.init.shared.b64 [%0], %1;" :: "r"(mbar), "r"(cnt) : "memory")

#define MBAR_WAIT(mbar, ph) do {                                              \
    uint32_t _done;                                                           \
    asm volatile("{\n\t.reg .pred p;\n\t"                                     \
        "mbarrier.try_wait.parity.acquire.cta.shared::cta.b64 p, [%1], %2;\n\t" \
        "selp.b32 %0,1,0,p;\n\t}"                                             \
        : "=r"(_done) : "r"(mbar), "r"(ph) : "memory");                       \
    if (!_done) {                                                             \
        asm volatile("{\n\t.reg .pred P1;\n\t"                                \
            "W1_%=:\n\t"                                                      \
            "mbarrier.try_wait.parity.acquire.cta.shared::cta.b64 P1, [%0], %1, 0x989680;\n\t" \
            "@P1 bra.uni W2_%=;\n\tbra.uni W1_%=;\n\tW2_%=:\n\t}"             \
            :: "r"(mbar), "r"(ph) : "memory");                                \
    }                                                                         \
} while (0)

#define TC_LD_X32(r, tmem)                                                    \
    asm volatile("tcgen05.ld.sync.aligned.32x32b.x32.b32 "                    \
        "{%0, %1, %2, %3, %4, %5, %6, %7, "                                   \
        " %8, %9, %10, %11, %12, %13, %14, %15, "                             \
        " %16, %17, %18, %19, %20, %21, %22, %23, "                           \
        " %24, %25, %26, %27, %28, %29, %30, %31}, [%32];"                    \
        : "=r"((r)[0]),  "=r"((r)[1]),  "=r"((r)[2]),  "=r"((r)[3]),          \
          "=r"((r)[4]),  "=r"((r)[5]),  "=r"((r)[6]),  "=r"((r)[7]),          \
          "=r"((r)[8]),  "=r"((r)[9]),  "=r"((r)[10]), "=r"((r)[11]),         \
          "=r"((r)[12]), "=r"((r)[13]), "=r"((r)[14]), "=r"((r)[15]),         \
          "=r"((r)[16]), "=r"((r)[17]), "=r"((r)[18]), "=r"((r)[19]),         \
          "=r"((r)[20]), "=r"((r)[21]), "=r"((r)[22]), "=r"((r)[23]),         \
          "=r"((r)[24]), "=r"((r)[25]), "=r"((r)[26]), "=r"((r)[27]),         \
          "=r"((r)[28]), "=r"((r)[29]), "=r"((r)[30]), "=r"((r)[31])          \
        : "r"(tmem))

__device__ __forceinline__ void mma_ss_f16(uint32_t d, uint64_t a, uint64_t b,
                                           uint32_t idesc, bool acc) {
    uint32_t e = acc ? 1u : 0u;
    asm volatile(
        "{\n\t.reg .pred p;\n\tsetp.ne.u32 p, %4, 0;\n\t"
        "tcgen05.mma.cta_group::1.kind::f16 [%0], %1, %2, %3, {%5,%5,%5,%5}, p;\n\t}"
        :: "r"(d), "l"(a), "l"(b), "r"(idesc), "r"(e), "r"(0u)
        : "memory");
}
#endif  // HAS_TCGEN05

// SW128 blocked-atom offset: atom = 8 rows x 64 bf16 (1024B), col-major atoms.
template <int ROWS>
__device__ __forceinline__ uint32_t sw_off(int r, int c) {
    uint32_t atom = (uint32_t)(r >> 3) + (uint32_t)(c >> 6) * (ROWS >> 3);
    uint32_t off = atom * 1024 + (r & 7) * 128 + (c & 63) * 2;
    return off ^ ((off >> 3) & 0x70);
}

__device__ __forceinline__ void split4(float4 v, unsigned long long& hi,
                                       unsigned long long& lo) {
    __nv_bfloat16 h0 = __float2bfloat16(v.x), h1 = __float2bfloat16(v.y);
    __nv_bfloat16 h2 = __float2bfloat16(v.z), h3 = __float2bfloat16(v.w);
    __nv_bfloat16 l0 = __float2bfloat16(v.x - __bfloat162float(h0));
    __nv_bfloat16 l1 = __float2bfloat16(v.y - __bfloat162float(h1));
    __nv_bfloat16 l2 = __float2bfloat16(v.z - __bfloat162float(h2));
    __nv_bfloat16 l3 = __float2bfloat16(v.w - __bfloat162float(h3));
    hi = (unsigned long long)__bfloat16_as_ushort(h0)
       | ((unsigned long long)__bfloat16_as_ushort(h1) << 16)
       | ((unsigned long long)__bfloat16_as_ushort(h2) << 32)
       | ((unsigned long long)__bfloat16_as_ushort(h3) << 48);
    lo = (unsigned long long)__bfloat16_as_ushort(l0)
       | ((unsigned long long)__bfloat16_as_ushort(l1) << 16)
       | ((unsigned long long)__bfloat16_as_ushort(l2) << 32)
       | ((unsigned long long)__bfloat16_as_ushort(l3) << 48);
}

// ---------------------------------------------------------------------------
// GEMM: C[r,:] = dinv[r] * (A[r,:] @ W)  (identical to R5 passing version)
// ---------------------------------------------------------------------------
template <int OUT>
__global__ void __launch_bounds__(128) tc_gemm(
    const float* __restrict__ A, const float* __restrict__ W,
    float* __restrict__ C, const float* __restrict__ dinv, int n)
{
    extern __shared__ char smem[];
    constexpr int K = 128;
    const int tid = threadIdx.x;
    const int row0 = blockIdx.x * 128;

#if HAS_TCGEN05
    constexpr uint32_t A_HI = 1024;
    constexpr uint32_t A_LO = A_HI + 128 * 256;
    constexpr uint32_t B_HI = A_LO + 128 * 256;
    constexpr uint32_t B_LO = B_HI + OUT * 256;

    const uint32_t sb = smem_u32(smem);
    const int wid = tid >> 5, lane = tid & 31;

    if (wid == 0) TC_ALLOC(sb + 0, 128);
    __syncthreads();
    uint32_t tmem;
    asm volatile("ld.shared.b32 %0, [%1];" : "=r"(tmem) : "r"(sb + 0));

    {
        int r = row0 + tid;
        if (r < n) {
            const float4* src = (const float4*)&A[(size_t)r * K];
#pragma unroll
            for (int c = 0; c < K; c += 4) {
                unsigned long long hi, lo;
                split4(src[c >> 2], hi, lo);
                uint32_t o = sw_off<128>(tid, c);
                *(unsigned long long*)(smem + A_HI + o) = hi;
                *(unsigned long long*)(smem + A_LO + o) = lo;
            }
        } else {
#pragma unroll
            for (int c = 0; c < K; c += 4) {
                uint32_t o = sw_off<128>(tid, c);
                *(unsigned long long*)(smem + A_HI + o) = 0ull;
                *(unsigned long long*)(smem + A_LO + o) = 0ull;
            }
        }
    }

    {
        int br, k0, kcnt;
        if (OUT == 128) { br = tid; k0 = 0; kcnt = K; }
        else { br = tid & (OUT - 1); k0 = (tid / OUT) * (K / (128 / OUT)); kcnt = K / (128 / OUT); }
#pragma unroll 4
        for (int k = k0; k < k0 + kcnt; k += 4) {
            float4 v = make_float4(W[(size_t)(k + 0) * OUT + br],
                                   W[(size_t)(k + 1) * OUT + br],
                                   W[(size_t)(k + 2) * OUT + br],
                                   W[(size_t)(k + 3) * OUT + br]);
            unsigned long long hi, lo;
            split4(v, hi, lo);
            uint32_t o = sw_off<OUT>(br, k);
            *(unsigned long long*)(smem + B_HI + o) = hi;
            *(unsigned long long*)(smem + B_LO + o) = lo;
        }
    }
    asm volatile("fence.proxy.async.shared::cta;" ::: "memory");
    __syncthreads();

    if (tid == 0) MBAR_INIT(sb + 8, 1);
    __syncthreads();

    if (wid == 0) {
        if (elect1()) {
            const uint64_t DB = (2ull << 61) | (1ull << 46) | (64ull << 32) | (1ull << 16);
            uint64_t dAhi = DB | (((sb + A_HI) >> 4) & 0x3FFF);
            uint64_t dAlo = DB | (((sb + A_LO) >> 4) & 0x3FFF);
            uint64_t dBhi = DB | (((sb + B_HI) >> 4) & 0x3FFF);
            uint64_t dBlo = DB | (((sb + B_LO) >> 4) & 0x3FFF);
            constexpr uint32_t idesc =
                (1u << 4) | (1u << 7) | (1u << 10) | ((OUT / 8) << 17) | (8u << 24);
            bool first = true;
#pragma unroll
            for (int s = 0; s < 8; s++) {
                uint64_t ao = (s < 4) ? (uint64_t)(s * 2) : (uint64_t)(1024 + (s - 4) * 2);
                uint64_t bo = (s < 4) ? (uint64_t)(s * 2) : (uint64_t)(OUT * 8 + (s - 4) * 2);
                mma_ss_f16(tmem, dAhi + ao, dBhi + bo, idesc, !first);
                first = false;
                mma_ss_f16(tmem, dAhi + ao, dBlo + bo, idesc, true);
                mma_ss_f16(tmem, dAlo + ao, dBhi + bo, idesc, true);
            }
            TC_COMMIT(sb + 8);
        }
    }

    MBAR_WAIT(sb + 8, 0);
    TC_FENCE_AFTER();

    {
        int r = row0 + wid * 32 + lane;
        float sc = (r < n) ? dinv[r] : 0.f;
#pragma unroll
        for (int ch = 0; ch < OUT; ch += 32) {
            uint32_t rg[32];
            TC_LD_X32(rg, tmem + ch);
            TC_WAIT_LD();
            if (r < n) {
#pragma unroll
                for (int j = 0; j < 32; j += 4) {
                    float4 v = make_float4(__uint_as_float(rg[j + 0]) * sc,
                                           __uint_as_float(rg[j + 1]) * sc,
                                           __uint_as_float(rg[j + 2]) * sc,
                                           __uint_as_float(rg[j + 3]) * sc);
                    *(float4*)&C[(size_t)r * OUT + ch + j] = v;
                }
            }
        }
    }

    __syncthreads();
    if (wid == 0) {
        if (elect1())
            asm volatile("mbarrier.inval.shared.b64 [%0];" :: "r"(sb + 8) : "memory");
        TC_DEALLOC(tmem, 128);
    }

#else  // FFMA fallback (virtual-arch build)
    constexpr int NTX = OUT / 8;
    constexpr int NTY = 128 / NTX;
    constexpr int RPT = 64 / NTY;
    float* As = (float*)smem;
    float* Bs = (float*)(smem + 8 * 64 * 4);

    const int tx = tid % NTX;
    const int ty = tid / NTX;

    for (int half = 0; half < 2; half++) {
        const int rbase = row0 + half * 64;
        float acc[RPT][8];
#pragma unroll
        for (int i = 0; i < RPT; i++)
#pragma unroll
            for (int j = 0; j < 8; j++) acc[i][j] = 0.f;

        for (int k0 = 0; k0 < K; k0 += 8) {
            int ar = tid >> 1, ac = (tid & 1) << 2;
            float4 av = make_float4(0.f, 0.f, 0.f, 0.f);
            if (rbase + ar < n)
                av = *(const float4*)&A[(size_t)(rbase + ar) * K + k0 + ac];
            As[(ac + 0) * 64 + ar] = av.x;
            As[(ac + 1) * 64 + ar] = av.y;
            As[(ac + 2) * 64 + ar] = av.z;
            As[(ac + 3) * 64 + ar] = av.w;
#pragma unroll
            for (int i = tid; i < 8 * OUT; i += 128)
                Bs[i] = W[(size_t)(k0 + i / OUT) * OUT + (i % OUT)];
            __syncthreads();
#pragma unroll
            for (int k = 0; k < 8; k++) {
                float a[RPT], b[8];
#pragma unroll
                for (int i = 0; i < RPT; i++) a[i] = As[k * 64 + ty * RPT + i];
                *(float4*)&b[0] = *(float4*)&Bs[k * OUT + tx * 8];
                *(float4*)&b[4] = *(float4*)&Bs[k * OUT + tx * 8 + 4];
#pragma unroll
                for (int i = 0; i < RPT; i++)
#pragma unroll
                    for (int j = 0; j < 8; j++) acc[i][j] += a[i] * b[j];
            }
            __syncthreads();
        }

#pragma unroll
        for (int i = 0; i < RPT; i++) {
            int r = rbase + ty * RPT + i;
            if (r < n) {
                float sc = dinv[r];
                float4 v0 = make_float4(acc[i][0] * sc, acc[i][1] * sc,
                                        acc[i][2] * sc, acc[i][3] * sc);
                float4 v1 = make_float4(acc[i][4] * sc, acc[i][5] * sc,
                                        acc[i][6] * sc, acc[i][7] * sc);
                *(float4*)&C[(size_t)r * OUT + tx * 8] = v0;
                *(float4*)&C[(size_t)r * OUT + tx * 8 + 4] = v1;
            }
        }
        __syncthreads();
    }
#endif
}

// ---------------------------------------------------------------------------
// edge decode (dtype-robust)
// ---------------------------------------------------------------------------
__global__ void probe_kernel(const int* __restrict__ w, int nwords) {
    if (threadIdx.x == 0 && blockIdx.x == 0) {
        int limit = nwords < 2048 ? nwords : 2048;
        int acc = 0;
        for (int i = 1; i < limit; i += 2) acc |= w[i];
        g_idx64 = (acc == 0) ? 1 : 0;
    }
}

__global__ void decode_kernel(const int* __restrict__ w, int E, int n) {
    int e = blockIdx.x * blockDim.x + threadIdx.x;
    if (e >= E) return;
    int s, d;
    if (g_idx64) {
        s = w[2 * (size_t)e];
        d = w[2 * ((size_t)E + e)];
    } else {
        s = w[e];
        d = w[(size_t)E + e];
    }
    if ((unsigned)s >= (unsigned)n) s = 0;
    if ((unsigned)d >= (unsigned)n) d = 0;
    g_src[e] = s;
    g_dst[e] = d;
}

// ---------------------------------------------------------------------------
// CSR build: histogram -> scan -> permute
// ---------------------------------------------------------------------------
__global__ void hist_kernel(const int* __restrict__ dst, int* cnt, int E) {
    int e = blockIdx.x * blockDim.x + threadIdx.x;
    if (e < E) atomicAdd(&cnt[dst[e]], 1);
}

__global__ void dinv_kernel(const int* __restrict__ cnt, float* dinv, int n) {
    int i = blockIdx.x * blockDim.x + threadIdx.x;
    if (i < n) dinv[i] = rsqrtf(1.0f + (float)cnt[i]);  // +1 self-loop
}

__global__ void scan1_kernel(const int* __restrict__ cnt, int* bsum, int n) {
    __shared__ int s[SCAN_B];
    int i = blockIdx.x * SCAN_B + threadIdx.x;
    s[threadIdx.x] = (i < n) ? cnt[i] : 0;
    __syncthreads();
    for (int off = SCAN_B / 2; off > 0; off >>= 1) {
        if (threadIdx.x < off) s[threadIdx.x] += s[threadIdx.x + off];
        __syncthreads();
    }
    if (threadIdx.x == 0) bsum[blockIdx.x] = s[0];
}

__global__ void scan2_kernel(const int* __restrict__ bsum, int* bpre,
                             int* rowptr, int nb, int n) {
    if (threadIdx.x == 0 && blockIdx.x == 0) {
        int run = 0;
        for (int b = 0; b < nb; b++) { bpre[b] = run; run += bsum[b]; }
        rowptr[n] = run;
    }
}

__global__ void scan3_kernel(const int* __restrict__ cnt,
                             const int* __restrict__ bpre,
                             int* rowptr, int* cursor, int n) {
    __shared__ int s[SCAN_B];
    int i = blockIdx.x * SCAN_B + threadIdx.x;
    int v = (i < n) ? cnt[i] : 0;
    s[threadIdx.x] = v;
    __syncthreads();
    // Hillis-Steele inclusive scan
    for (int off = 1; off < SCAN_B; off <<= 1) {
        int t = (threadIdx.x >= off) ? s[threadIdx.x - off] : 0;
        __syncthreads();
        s[threadIdx.x] += t;
        __syncthreads();
    }
    if (i < n) {
        int excl = s[threadIdx.x] - v + bpre[blockIdx.x];
        rowptr[i] = excl;
        cursor[i] = excl;
    }
}

__global__ void permute_kernel(const int* __restrict__ src,
                               const int* __restrict__ dst,
                               int* cursor, int* sorted, int E) {
    int e = blockIdx.x * blockDim.x + threadIdx.x;
    if (e >= E) return;
    int pos = atomicAdd(&cursor[dst[e]], 1);
    sorted[pos] = src[e];
}

// ---------------------------------------------------------------------------
// Fused aggregate: res[d] = f( dinv[d] * (sum_in h[src] + h[d]) + bias )
// One warp per dst node; lanes hold DIM/32 floats each; 4-way edge unroll.
// ---------------------------------------------------------------------------
template <int DIM, bool RELU>
__global__ void __launch_bounds__(256) aggregate_kernel(
    const int* __restrict__ rowptr, const int* __restrict__ sorted,
    const float* __restrict__ h, float* __restrict__ res,
    const float* __restrict__ dinv, const float* __restrict__ bias, int n)
{
    constexpr int VPL = DIM / 32;  // floats per lane: 4 (D=128) or 2 (D=64)
    int node = (int)((blockIdx.x * (long long)blockDim.x + threadIdx.x) >> 5);
    int lane = threadIdx.x & 31;
    if (node >= n) return;

    const int beg = rowptr[node];
    const int end = rowptr[node + 1];
    const int col = lane * VPL;

    float acc[VPL];
    // self-loop init
    if (VPL == 4) {
        float4 v = *(const float4*)&h[(size_t)node * DIM + col];
        acc[0] = v.x; acc[1] = v.y; acc[2] = v.z; acc[3] = v.w;
    } else {
        float2 v = *(const float2*)&h[(size_t)node * DIM + col];
        acc[0] = v.x; acc[1] = v.y;
    }

    int e = beg;
    for (; e + 4 <= end; e += 4) {
        int s0 = sorted[e + 0], s1 = sorted[e + 1];
        int s2 = sorted[e + 2], s3 = sorted[e + 3];
        if (VPL == 4) {
            float4 v0 = *(const float4*)&h[(size_t)s0 * DIM + col];
            float4 v1 = *(const float4*)&h[(size_t)s1 * DIM + col];
            float4 v2 = *(const float4*)&h[(size_t)s2 * DIM + col];
            float4 v3 = *(const float4*)&h[(size_t)s3 * DIM + col];
            acc[0] += (v0.x + v1.x) + (v2.x + v3.x);
            acc[1] += (v0.y + v1.y) + (v2.y + v3.y);
            acc[2] += (v0.z + v1.z) + (v2.z + v3.z);
            acc[3] += (v0.w + v1.w) + (v2.w + v3.w);
        } else {
            float2 v0 = *(const float2*)&h[(size_t)s0 * DIM + col];
            float2 v1 = *(const float2*)&h[(size_t)s1 * DIM + col];
            float2 v2 = *(const float2*)&h[(size_t)s2 * DIM + col];
            float2 v3 = *(const float2*)&h[(size_t)s3 * DIM + col];
            acc[0] += (v0.x + v1.x) + (v2.x + v3.x);
            acc[1] += (v0.y + v1.y) + (v2.y + v3.y);
        }
    }
    for (; e < end; e++) {
        int s = sorted[e];
        if (VPL == 4) {
            float4 v = *(const float4*)&h[(size_t)s * DIM + col];
            acc[0] += v.x; acc[1] += v.y; acc[2] += v.z; acc[3] += v.w;
        } else {
            float2 v = *(const float2*)&h[(size_t)s * DIM + col];
            acc[0] += v.x; acc[1] += v.y;
        }
    }

    float di = dinv[node];
    if (VPL == 4) {
        float4 b = *(const float4*)&bias[col];
        float4 r;
        r.x = di * acc[0] + b.x;
        r.y = di * acc[1] + b.y;
        r.z = di * acc[2] + b.z;
        r.w = di * acc[3] + b.w;
        if (RELU) {
            r.x = fmaxf(r.x, 0.f); r.y = fmaxf(r.y, 0.f);
            r.z = fmaxf(r.z, 0.f); r.w = fmaxf(r.w, 0.f);
        }
        *(float4*)&res[(size_t)node * DIM + col] = r;
    } else {
        float2 b = *(const float2*)&bias[col];
        float2 r;
        r.x = di * acc[0] + b.x;
        r.y = di * acc[1] + b.y;
        if (RELU) { r.x = fmaxf(r.x, 0.f); r.y = fmaxf(r.y, 0.f); }
        *(float2*)&res[(size_t)node * DIM + col] = r;
    }
}

// ---------------------------------------------------------------------------
// launch
// ---------------------------------------------------------------------------
static inline int cdiv(long long a, long long b) { return (int)((a + b - 1) / b); }

extern "C" void kernel_launch(void* const* d_in, const int* in_sizes, int n_in,
                              void* d_out, int out_size)
{
    const float* x   = (const float*)d_in[0];
    const int*   eiw = (const int*)d_in[1];
    const float* W1  = (const float*)d_in[2];
    const float* b1  = (const float*)d_in[3];
    const float* W2  = (const float*)d_in[4];
    const float* b2  = (const float*)d_in[5];
    float*       out = (float*)d_out;

    const int n = in_sizes[0] / D0;
    int E = in_sizes[1] / 2;
    if (E > EMAX) E = EMAX;
    const int NB = cdiv(n, SCAN_B);

    float *dinv, *h, *agg;
    int *srcp, *dstp, *sorted, *cnt, *rowptr, *cursor, *bsum, *bpre;
    cudaGetSymbolAddress((void**)&dinv,   g_dinv);
    cudaGetSymbolAddress((void**)&h,      g_h);
    cudaGetSymbolAddress((void**)&agg,    g_agg);
    cudaGetSymbolAddress((void**)&srcp,   g_src);
    cudaGetSymbolAddress((void**)&dstp,   g_dst);
    cudaGetSymbolAddress((void**)&sorted, g_sorted);
    cudaGetSymbolAddress((void**)&cnt,    g_cnt);
    cudaGetSymbolAddress((void**)&rowptr, g_rowptr);
    cudaGetSymbolAddress((void**)&cursor, g_cursor);
    cudaGetSymbolAddress((void**)&bsum,   g_bsum);
    cudaGetSymbolAddress((void**)&bpre,   g_bpre);

    constexpr int SMEM1 = 1024 + 2 * 128 * 256 + 2 * 128 * 256;
    constexpr int SMEM2 = 1024 + 2 * 128 * 256 + 2 * 64 * 256;
    cudaFuncSetAttribute(tc_gemm<128>, cudaFuncAttributeMaxDynamicSharedMemorySize, SMEM1);
    cudaFuncSetAttribute(tc_gemm<64>,  cudaFuncAttributeMaxDynamicSharedMemorySize, SMEM2);

    // --- decode + CSR build ---
    probe_kernel<<<1, 32>>>(eiw, in_sizes[1]);
    decode_kernel<<<cdiv(E, 256), 256>>>(eiw, E, n);
    cudaMemsetAsync(cnt, 0, (size_t)n * sizeof(int));
    hist_kernel<<<cdiv(E, 256), 256>>>(dstp, cnt, E);
    dinv_kernel<<<cdiv(n, 256), 256>>>(cnt, dinv, n);
    scan1_kernel<<<NB, SCAN_B>>>(cnt, bsum, n);
    scan2_kernel<<<1, 32>>>(bsum, bpre, rowptr, NB, n);
    scan3_kernel<<<NB, SCAN_B>>>(cnt, bpre, rowptr, cursor, n);
    permute_kernel<<<cdiv(E, 256), 256>>>(srcp, dstp, cursor, sorted, E);

    // --- layer 1 ---
    tc_gemm<D1><<<cdiv(n, 128), 128, SMEM1>>>(x, W1, h, dinv, n);
    aggregate_kernel<D1, true><<<cdiv(n, 8), 256>>>(rowptr, sorted, h, agg, dinv, b1, n);

    // --- layer 2 ---
    tc_gemm<D2><<<cdiv(n, 128), 128, SMEM2>>>(agg, W2, h, dinv, n);
    aggregate_kernel<D2, false><<<cdiv(n, 8), 256>>>(rowptr, sorted, h, out, dinv, b2, n);
}

// round 8
// speedup vs baseline: 1.7846x; 1.0288x over previous
#include <cuda_runtime.h>
#include <cuda_bf16.h>
#include <cstdint>

// ---------------------------------------------------------------------------
// GCNEncoder: out = GCNConv2( relu( GCNConv1(x) ) )
// Prescale: h_s = (x@W)*dinv ; agg[d] = sum_in h_s[src] ; out = dinv*(agg+h_s)+b
// CSR build: fused decode+hist+rank -> scan (dinv fused) -> atomic-free scatter.
// GEMMs: tcgen05 bf16 hi/lo split (sm_103a) / FFMA fallback (compute_103).
// ---------------------------------------------------------------------------

#define NMAX 100000
#define EMAX 1600000
#define D0 128
#define D1 128
#define D2 64
#define SCAN_B 1024

#if defined(__CUDA_ARCH_FEAT_SM103_ALL) || defined(__CUDA_ARCH_FEAT_SM100_ALL) || \
    (defined(__CUDA_ARCH_SPECIFIC__) && (__CUDA_ARCH__ >= 1000))
#define HAS_TCGEN05 1
#else
#define HAS_TCGEN05 0
#endif

__device__ float g_dinv[NMAX];
__device__ float g_h[(size_t)NMAX * D1];
__device__ float g_agg[(size_t)NMAX * D1];
__device__ int   g_src[EMAX];
__device__ int   g_dst[EMAX];
__device__ int   g_rank[EMAX];
__device__ int   g_sorted[EMAX];
__device__ int   g_cnt[NMAX];
__device__ int   g_rowptr[NMAX + 1];
__device__ int   g_bsum[128];
__device__ int   g_bpre[128];
__device__ int   g_idx64;

// ---------------------------------------------------------------------------
// PTX helpers
// ---------------------------------------------------------------------------
__device__ __forceinline__ uint32_t smem_u32(const void* p) {
    uint32_t a;
    asm("{ .reg .u64 t; cvta.to.shared.u64 t, %1; cvt.u32.u64 %0, t; }"
        : "=r"(a) : "l"(p));
    return a;
}

#if HAS_TCGEN05
__device__ __forceinline__ uint32_t elect1() {
    uint32_t p;
    asm volatile("{ .reg .pred p; elect.sync _|p, 0xFFFFFFFF; selp.b32 %0,1,0,p; }"
                 : "=r"(p));
    return p;
}

#define TC_ALLOC(smem_addr, ncols) \
    asm volatile("tcgen05.alloc.cta_group::1.sync.aligned.shared::cta.b32 [%0], %1;" \
                 :: "r"(smem_addr), "r"(ncols) : "memory")
#define TC_DEALLOC(tmem, ncols) \
    asm volatile("tcgen05.dealloc.cta_group::1.sync.aligned.b32 %0, %1;" \
                 :: "r"(tmem), "r"(ncols))
#define TC_COMMIT(mbar) \
    asm volatile("tcgen05.commit.cta_group::1.mbarrier::arrive::one.shared::cluster.b64 [%0];" \
                 :: "r"(mbar) : "memory")
#define TC_WAIT_LD() asm volatile("tcgen05.wait::ld.sync.aligned;" ::: "memory")
#define TC_FENCE_AFTER() asm volatile("tcgen05.fence::after_thread_sync;" ::: "memory")
#define MBAR_INIT(mbar, cnt) \
    asm volatile("mbarrier.init.shared.b64 [%0], %1;" :: "r"(mbar), "r"(cnt) : "memory")

#define MBAR_WAIT(mbar, ph) do {                                              \
    uint32_t _done;                                                           \
    asm volatile("{\n\t.reg .pred p;\n\t"                                     \
        "mbarrier.try_wait.parity.acquire.cta.shared::cta.b64 p, [%1], %2;\n\t" \
        "selp.b32 %0,1,0,p;\n\t}"                                             \
        : "=r"(_done) : "r"(mbar), "r"(ph) : "memory");                       \
    if (!_done) {                                                             \
        asm volatile("{\n\t.reg .pred P1;\n\t"                                \
            "W1_%=:\n\t"                                                      \
            "mbarrier.try_wait.parity.acquire.cta.shared::cta.b64 P1, [%0], %1, 0x989680;\n\t" \
            "@P1 bra.uni W2_%=;\n\tbra.uni W1_%=;\n\tW2_%=:\n\t}"             \
            :: "r"(mbar), "r"(ph) : "memory");                                \
    }                                                                         \
} while (0)

#define TC_LD_X32(r, tmem)                                                    \
    asm volatile("tcgen05.ld.sync.aligned.32x32b.x32.b32 "                    \
        "{%0, %1, %2, %3, %4, %5, %6, %7, "                                   \
        " %8, %9, %10, %11, %12, %13, %14, %15, "                             \
        " %16, %17, %18, %19, %20, %21, %22, %23, "                           \
        " %24, %25, %26, %27, %28, %29, %30, %31}, [%32];"                    \
        : "=r"((r)[0]),  "=r"((r)[1]),  "=r"((r)[2]),  "=r"((r)[3]),          \
          "=r"((r)[4]),  "=r"((r)[5]),  "=r"((r)[6]),  "=r"((r)[7]),          \
          "=r"((r)[8]),  "=r"((r)[9]),  "=r"((r)[10]), "=r"((r)[11]),         \
          "=r"((r)[12]), "=r"((r)[13]), "=r"((r)[14]), "=r"((r)[15]),         \
          "=r"((r)[16]), "=r"((r)[17]), "=r"((r)[18]), "=r"((r)[19]),         \
          "=r"((r)[20]), "=r"((r)[21]), "=r"((r)[22]), "=r"((r)[23]),         \
          "=r"((r)[24]), "=r"((r)[25]), "=r"((r)[26]), "=r"((r)[27]),         \
          "=r"((r)[28]), "=r"((r)[29]), "=r"((r)[30]), "=r"((r)[31])          \
        : "r"(tmem))

__device__ __forceinline__ void mma_ss_f16(uint32_t d, uint64_t a, uint64_t b,
                                           uint32_t idesc, bool acc) {
    uint32_t e = acc ? 1u : 0u;
    asm volatile(
        "{\n\t.reg .pred p;\n\tsetp.ne.u32 p, %4, 0;\n\t"
        "tcgen05.mma.cta_group::1.kind::f16 [%0], %1, %2, %3, {%5,%5,%5,%5}, p;\n\t}"
        :: "r"(d), "l"(a), "l"(b), "r"(idesc), "r"(e), "r"(0u)
        : "memory");
}
#endif  // HAS_TCGEN05

// SW128 blocked-atom offset: atom = 8 rows x 64 bf16 (1024B), col-major atoms.
template <int ROWS>
__device__ __forceinline__ uint32_t sw_off(int r, int c) {
    uint32_t atom = (uint32_t)(r >> 3) + (uint32_t)(c >> 6) * (ROWS >> 3);
    uint32_t off = atom * 1024 + (r & 7) * 128 + (c & 63) * 2;
    return off ^ ((off >> 3) & 0x70);
}

__device__ __forceinline__ void split4(float4 v, unsigned long long& hi,
                                       unsigned long long& lo) {
    __nv_bfloat16 h0 = __float2bfloat16(v.x), h1 = __float2bfloat16(v.y);
    __nv_bfloat16 h2 = __float2bfloat16(v.z), h3 = __float2bfloat16(v.w);
    __nv_bfloat16 l0 = __float2bfloat16(v.x - __bfloat162float(h0));
    __nv_bfloat16 l1 = __float2bfloat16(v.y - __bfloat162float(h1));
    __nv_bfloat16 l2 = __float2bfloat16(v.z - __bfloat162float(h2));
    __nv_bfloat16 l3 = __float2bfloat16(v.w - __bfloat162float(h3));
    hi = (unsigned long long)__bfloat16_as_ushort(h0)
       | ((unsigned long long)__bfloat16_as_ushort(h1) << 16)
       | ((unsigned long long)__bfloat16_as_ushort(h2) << 32)
       | ((unsigned long long)__bfloat16_as_ushort(h3) << 48);
    lo = (unsigned long long)__bfloat16_as_ushort(l0)
       | ((unsigned long long)__bfloat16_as_ushort(l1) << 16)
       | ((unsigned long long)__bfloat16_as_ushort(l2) << 32)
       | ((unsigned long long)__bfloat16_as_ushort(l3) << 48);
}

// ---------------------------------------------------------------------------
// GEMM: C[r,:] = dinv[r] * (A[r,:] @ W)  (identical to R6 passing version)
// ---------------------------------------------------------------------------
template <int OUT>
__global__ void __launch_bounds__(128) tc_gemm(
    const float* __restrict__ A, const float* __restrict__ W,
    float* __restrict__ C, const float* __restrict__ dinv, int n)
{
    extern __shared__ char smem[];
    constexpr int K = 128;
    const int tid = threadIdx.x;
    const int row0 = blockIdx.x * 128;

#if HAS_TCGEN05
    constexpr uint32_t A_HI = 1024;
    constexpr uint32_t A_LO = A_HI + 128 * 256;
    constexpr uint32_t B_HI = A_LO + 128 * 256;
    constexpr uint32_t B_LO = B_HI + OUT * 256;

    const uint32_t sb = smem_u32(smem);
    const int wid = tid >> 5, lane = tid & 31;

    if (wid == 0) TC_ALLOC(sb + 0, 128);
    __syncthreads();
    uint32_t tmem;
    asm volatile("ld.shared.b32 %0, [%1];" : "=r"(tmem) : "r"(sb + 0));

    {
        int r = row0 + tid;
        if (r < n) {
            const float4* src = (const float4*)&A[(size_t)r * K];
#pragma unroll
            for (int c = 0; c < K; c += 4) {
                unsigned long long hi, lo;
                split4(src[c >> 2], hi, lo);
                uint32_t o = sw_off<128>(tid, c);
                *(unsigned long long*)(smem + A_HI + o) = hi;
                *(unsigned long long*)(smem + A_LO + o) = lo;
            }
        } else {
#pragma unroll
            for (int c = 0; c < K; c += 4) {
                uint32_t o = sw_off<128>(tid, c);
                *(unsigned long long*)(smem + A_HI + o) = 0ull;
                *(unsigned long long*)(smem + A_LO + o) = 0ull;
            }
        }
    }

    {
        int br, k0, kcnt;
        if (OUT == 128) { br = tid; k0 = 0; kcnt = K; }
        else { br = tid & (OUT - 1); k0 = (tid / OUT) * (K / (128 / OUT)); kcnt = K / (128 / OUT); }
#pragma unroll 4
        for (int k = k0; k < k0 + kcnt; k += 4) {
            float4 v = make_float4(W[(size_t)(k + 0) * OUT + br],
                                   W[(size_t)(k + 1) * OUT + br],
                                   W[(size_t)(k + 2) * OUT + br],
                                   W[(size_t)(k + 3) * OUT + br]);
            unsigned long long hi, lo;
            split4(v, hi, lo);
            uint32_t o = sw_off<OUT>(br, k);
            *(unsigned long long*)(smem + B_HI + o) = hi;
            *(unsigned long long*)(smem + B_LO + o) = lo;
        }
    }
    asm volatile("fence.proxy.async.shared::cta;" ::: "memory");
    __syncthreads();

    if (tid == 0) MBAR_INIT(sb + 8, 1);
    __syncthreads();

    if (wid == 0) {
        if (elect1()) {
            const uint64_t DB = (2ull << 61) | (1ull << 46) | (64ull << 32) | (1ull << 16);
            uint64_t dAhi = DB | (((sb + A_HI) >> 4) & 0x3FFF);
            uint64_t dAlo = DB | (((sb + A_LO) >> 4) & 0x3FFF);
            uint64_t dBhi = DB | (((sb + B_HI) >> 4) & 0x3FFF);
            uint64_t dBlo = DB | (((sb + B_LO) >> 4) & 0x3FFF);
            constexpr uint32_t idesc =
                (1u << 4) | (1u << 7) | (1u << 10) | ((OUT / 8) << 17) | (8u << 24);
            bool first = true;
#pragma unroll
            for (int s = 0; s < 8; s++) {
                uint64_t ao = (s < 4) ? (uint64_t)(s * 2) : (uint64_t)(1024 + (s - 4) * 2);
                uint64_t bo = (s < 4) ? (uint64_t)(s * 2) : (uint64_t)(OUT * 8 + (s - 4) * 2);
                mma_ss_f16(tmem, dAhi + ao, dBhi + bo, idesc, !first);
                first = false;
                mma_ss_f16(tmem, dAhi + ao, dBlo + bo, idesc, true);
                mma_ss_f16(tmem, dAlo + ao, dBhi + bo, idesc, true);
            }
            TC_COMMIT(sb + 8);
        }
    }

    MBAR_WAIT(sb + 8, 0);
    TC_FENCE_AFTER();

    {
        int r = row0 + wid * 32 + lane;
        float sc = (r < n) ? dinv[r] : 0.f;
#pragma unroll
        for (int ch = 0; ch < OUT; ch += 32) {
            uint32_t rg[32];
            TC_LD_X32(rg, tmem + ch);
            TC_WAIT_LD();
            if (r < n) {
#pragma unroll
                for (int j = 0; j < 32; j += 4) {
                    float4 v = make_float4(__uint_as_float(rg[j + 0]) * sc,
                                           __uint_as_float(rg[j + 1]) * sc,
                                           __uint_as_float(rg[j + 2]) * sc,
                                           __uint_as_float(rg[j + 3]) * sc);
                    *(float4*)&C[(size_t)r * OUT + ch + j] = v;
                }
            }
        }
    }

    __syncthreads();
    if (wid == 0) {
        if (elect1())
            asm volatile("mbarrier.inval.shared.b64 [%0];" :: "r"(sb + 8) : "memory");
        TC_DEALLOC(tmem, 128);
    }

#else  // FFMA fallback (virtual-arch build)
    constexpr int NTX = OUT / 8;
    constexpr int NTY = 128 / NTX;
    constexpr int RPT = 64 / NTY;
    float* As = (float*)smem;
    float* Bs = (float*)(smem + 8 * 64 * 4);

    const int tx = tid % NTX;
    const int ty = tid / NTX;

    for (int half = 0; half < 2; half++) {
        const int rbase = row0 + half * 64;
        float acc[RPT][8];
#pragma unroll
        for (int i = 0; i < RPT; i++)
#pragma unroll
            for (int j = 0; j < 8; j++) acc[i][j] = 0.f;

        for (int k0 = 0; k0 < K; k0 += 8) {
            int ar = tid >> 1, ac = (tid & 1) << 2;
            float4 av = make_float4(0.f, 0.f, 0.f, 0.f);
            if (rbase + ar < n)
                av = *(const float4*)&A[(size_t)(rbase + ar) * K + k0 + ac];
            As[(ac + 0) * 64 + ar] = av.x;
            As[(ac + 1) * 64 + ar] = av.y;
            As[(ac + 2) * 64 + ar] = av.z;
            As[(ac + 3) * 64 + ar] = av.w;
#pragma unroll
            for (int i = tid; i < 8 * OUT; i += 128)
                Bs[i] = W[(size_t)(k0 + i / OUT) * OUT + (i % OUT)];
            __syncthreads();
#pragma unroll
            for (int k = 0; k < 8; k++) {
                float a[RPT], b[8];
#pragma unroll
                for (int i = 0; i < RPT; i++) a[i] = As[k * 64 + ty * RPT + i];
                *(float4*)&b[0] = *(float4*)&Bs[k * OUT + tx * 8];
                *(float4*)&b[4] = *(float4*)&Bs[k * OUT + tx * 8 + 4];
#pragma unroll
                for (int i = 0; i < RPT; i++)
#pragma unroll
                    for (int j = 0; j < 8; j++) acc[i][j] += a[i] * b[j];
            }
            __syncthreads();
        }

#pragma unroll
        for (int i = 0; i < RPT; i++) {
            int r = rbase + ty * RPT + i;
            if (r < n) {
                float sc = dinv[r];
                float4 v0 = make_float4(acc[i][0] * sc, acc[i][1] * sc,
                                        acc[i][2] * sc, acc[i][3] * sc);
                float4 v1 = make_float4(acc[i][4] * sc, acc[i][5] * sc,
                                        acc[i][6] * sc, acc[i][7] * sc);
                *(float4*)&C[(size_t)r * OUT + tx * 8] = v0;
                *(float4*)&C[(size_t)r * OUT + tx * 8 + 4] = v1;
            }
        }
        __syncthreads();
    }
#endif
}

// ---------------------------------------------------------------------------
// CSR build, pass 1: decode (dtype-robust) + histogram + per-edge rank
// ---------------------------------------------------------------------------
__global__ void probe_kernel(const int* __restrict__ w, int nwords) {
    if (threadIdx.x == 0 && blockIdx.x == 0) {
        int limit = nwords < 2048 ? nwords : 2048;
        int acc = 0;
        for (int i = 1; i < limit; i += 2) acc |= w[i];
        g_idx64 = (acc == 0) ? 1 : 0;
    }
}

__global__ void decode_hist_kernel(const int* __restrict__ w, int* cnt,
                                   int E, int n) {
    int e = blockIdx.x * blockDim.x + threadIdx.x;
    if (e >= E) return;
    int s, d;
    if (g_idx64) {
        s = w[2 * (size_t)e];
        d = w[2 * ((size_t)E + e)];
    } else {
        s = w[e];
        d = w[(size_t)E + e];
    }
    if ((unsigned)s >= (unsigned)n) s = 0;
    if ((unsigned)d >= (unsigned)n) d = 0;
    g_src[e] = s;
    g_dst[e] = d;
    g_rank[e] = atomicAdd(&cnt[d], 1);
}

// ---------------------------------------------------------------------------
// scan (3 kernels) -- scan3 also emits dinv = rsqrt(1+cnt)
// ---------------------------------------------------------------------------
__global__ void scan1_kernel(const int* __restrict__ cnt, int* bsum, int n) {
    __shared__ int s[SCAN_B];
    int i = blockIdx.x * SCAN_B + threadIdx.x;
    s[threadIdx.x] = (i < n) ? cnt[i] : 0;
    __syncthreads();
    for (int off = SCAN_B / 2; off > 0; off >>= 1) {
        if (threadIdx.x < off) s[threadIdx.x] += s[threadIdx.x + off];
        __syncthreads();
    }
    if (threadIdx.x == 0) bsum[blockIdx.x] = s[0];
}

__global__ void scan2_kernel(const int* __restrict__ bsum, int* bpre,
                             int* rowptr, int nb, int n) {
    if (threadIdx.x == 0 && blockIdx.x == 0) {
        int run = 0;
        for (int b = 0; b < nb; b++) { bpre[b] = run; run += bsum[b]; }
        rowptr[n] = run;
    }
}

__global__ void scan3_kernel(const int* __restrict__ cnt,
                             const int* __restrict__ bpre,
                             int* rowptr, float* dinv, int n) {
    __shared__ int s[SCAN_B];
    int i = blockIdx.x * SCAN_B + threadIdx.x;
    int v = (i < n) ? cnt[i] : 0;
    s[threadIdx.x] = v;
    __syncthreads();
    for (int off = 1; off < SCAN_B; off <<= 1) {
        int t = (threadIdx.x >= off) ? s[threadIdx.x - off] : 0;
        __syncthreads();
        s[threadIdx.x] += t;
        __syncthreads();
    }
    if (i < n) {
        rowptr[i] = s[threadIdx.x] - v + bpre[blockIdx.x];
        dinv[i] = rsqrtf(1.0f + (float)v);  // +1 self-loop
    }
}

// ---------------------------------------------------------------------------
// CSR build, pass 2: atomic-free scatter using precomputed ranks
// ---------------------------------------------------------------------------
__global__ void scatter_sort_kernel(const int* __restrict__ src,
                                    const int* __restrict__ dst,
                                    const int* __restrict__ rank,
                                    const int* __restrict__ rowptr,
                                    int* sorted, int E) {
    int e = blockIdx.x * blockDim.x + threadIdx.x;
    if (e >= E) return;
    sorted[rowptr[dst[e]] + rank[e]] = src[e];
}

// ---------------------------------------------------------------------------
// Fused aggregate: res[d] = f( dinv[d] * (sum_in h[src] + h[d]) + bias )
// One warp per dst node; lanes hold DIM/32 floats each; 4-way edge unroll.
// ---------------------------------------------------------------------------
template <int DIM, bool RELU>
__global__ void __launch_bounds__(256) aggregate_kernel(
    const int* __restrict__ rowptr, const int* __restrict__ sorted,
    const float* __restrict__ h, float* __restrict__ res,
    const float* __restrict__ dinv, const float* __restrict__ bias, int n)
{
    constexpr int VPL = DIM / 32;  // floats per lane: 4 (D=128) or 2 (D=64)
    int node = (int)((blockIdx.x * (long long)blockDim.x + threadIdx.x) >> 5);
    int lane = threadIdx.x & 31;
    if (node >= n) return;

    const int beg = rowptr[node];
    const int end = rowptr[node + 1];
    const int col = lane * VPL;

    float acc[VPL];
    if (VPL == 4) {
        float4 v = *(const float4*)&h[(size_t)node * DIM + col];
        acc[0] = v.x; acc[1] = v.y; acc[2] = v.z; acc[3] = v.w;
    } else {
        float2 v = *(const float2*)&h[(size_t)node * DIM + col];
        acc[0] = v.x; acc[1] = v.y;
    }

    int e = beg;
    for (; e + 4 <= end; e += 4) {
        int s0 = sorted[e + 0], s1 = sorted[e + 1];
        int s2 = sorted[e + 2], s3 = sorted[e + 3];
        if (VPL == 4) {
            float4 v0 = *(const float4*)&h[(size_t)s0 * DIM + col];
            float4 v1 = *(const float4*)&h[(size_t)s1 * DIM + col];
            float4 v2 = *(const float4*)&h[(size_t)s2 * DIM + col];
            float4 v3 = *(const float4*)&h[(size_t)s3 * DIM + col];
            acc[0] += (v0.x + v1.x) + (v2.x + v3.x);
            acc[1] += (v0.y + v1.y) + (v2.y + v3.y);
            acc[2] += (v0.z + v1.z) + (v2.z + v3.z);
            acc[3] += (v0.w + v1.w) + (v2.w + v3.w);
        } else {
            float2 v0 = *(const float2*)&h[(size_t)s0 * DIM + col];
            float2 v1 = *(const float2*)&h[(size_t)s1 * DIM + col];
            float2 v2 = *(const float2*)&h[(size_t)s2 * DIM + col];
            float2 v3 = *(const float2*)&h[(size_t)s3 * DIM + col];
            acc[0] += (v0.x + v1.x) + (v2.x + v3.x);
            acc[1] += (v0.y + v1.y) + (v2.y + v3.y);
        }
    }
    for (; e < end; e++) {
        int s = sorted[e];
        if (VPL == 4) {
            float4 v = *(const float4*)&h[(size_t)s * DIM + col];
            acc[0] += v.x; acc[1] += v.y; acc[2] += v.z; acc[3] += v.w;
        } else {
            float2 v = *(const float2*)&h[(size_t)s * DIM + col];
            acc[0] += v.x; acc[1] += v.y;
        }
    }

    float di = dinv[node];
    if (VPL == 4) {
        float4 b = *(const float4*)&bias[col];
        float4 r;
        r.x = di * acc[0] + b.x;
        r.y = di * acc[1] + b.y;
        r.z = di * acc[2] + b.z;
        r.w = di * acc[3] + b.w;
        if (RELU) {
            r.x = fmaxf(r.x, 0.f); r.y = fmaxf(r.y, 0.f);
            r.z = fmaxf(r.z, 0.f); r.w = fmaxf(r.w, 0.f);
        }
        *(float4*)&res[(size_t)node * DIM + col] = r;
    } else {
        float2 b = *(const float2*)&bias[col];
        float2 r;
        r.x = di * acc[0] + b.x;
        r.y = di * acc[1] + b.y;
        if (RELU) { r.x = fmaxf(r.x, 0.f); r.y = fmaxf(r.y, 0.f); }
        *(float2*)&res[(size_t)node * DIM + col] = r;
    }
}

// ---------------------------------------------------------------------------
// launch
// ---------------------------------------------------------------------------
static inline int cdiv(long long a, long long b) { return (int)((a + b - 1) / b); }

extern "C" void kernel_launch(void* const* d_in, const int* in_sizes, int n_in,
                              void* d_out, int out_size)
{
    const float* x   = (const float*)d_in[0];
    const int*   eiw = (const int*)d_in[1];
    const float* W1  = (const float*)d_in[2];
    const float* b1  = (const float*)d_in[3];
    const float* W2  = (const float*)d_in[4];
    const float* b2  = (const float*)d_in[5];
    float*       out = (float*)d_out;

    const int n = in_sizes[0] / D0;
    int E = in_sizes[1] / 2;
    if (E > EMAX) E = EMAX;
    const int NB = cdiv(n, SCAN_B);

    float *dinv, *h, *agg;
    int *srcp, *dstp, *rankp, *sorted, *cnt, *rowptr, *bsum, *bpre;
    cudaGetSymbolAddress((void**)&dinv,   g_dinv);
    cudaGetSymbolAddress((void**)&h,      g_h);
    cudaGetSymbolAddress((void**)&agg,    g_agg);
    cudaGetSymbolAddress((void**)&srcp,   g_src);
    cudaGetSymbolAddress((void**)&dstp,   g_dst);
    cudaGetSymbolAddress((void**)&rankp,  g_rank);
    cudaGetSymbolAddress((void**)&sorted, g_sorted);
    cudaGetSymbolAddress((void**)&cnt,    g_cnt);
    cudaGetSymbolAddress((void**)&rowptr, g_rowptr);
    cudaGetSymbolAddress((void**)&bsum,   g_bsum);
    cudaGetSymbolAddress((void**)&bpre,   g_bpre);

    constexpr int SMEM1 = 1024 + 2 * 128 * 256 + 2 * 128 * 256;
    constexpr int SMEM2 = 1024 + 2 * 128 * 256 + 2 * 64 * 256;
    cudaFuncSetAttribute(tc_gemm<128>, cudaFuncAttributeMaxDynamicSharedMemorySize, SMEM1);
    cudaFuncSetAttribute(tc_gemm<64>,  cudaFuncAttributeMaxDynamicSharedMemorySize, SMEM2);

    // --- CSR build ---
    probe_kernel<<<1, 32>>>(eiw, in_sizes[1]);
    cudaMemsetAsync(cnt, 0, (size_t)n * sizeof(int));
    decode_hist_kernel<<<cdiv(E, 256), 256>>>(eiw, cnt, E, n);
    scan1_kernel<<<NB, SCAN_B>>>(cnt, bsum, n);
    scan2_kernel<<<1, 32>>>(bsum, bpre, rowptr, NB, n);
    scan3_kernel<<<NB, SCAN_B>>>(cnt, bpre, rowptr, dinv, n);
    scatter_sort_kernel<<<cdiv(E, 256), 256>>>(srcp, dstp, rankp, rowptr, sorted, E);

    // --- layer 1 ---
    tc_gemm<D1><<<cdiv(n, 128), 128, SMEM1>>>(x, W1, h, dinv, n);
    aggregate_kernel<D1, true><<<cdiv(n, 8), 256>>>(rowptr, sorted, h, agg, dinv, b1, n);

    // --- layer 2 ---
    tc_gemm<D2><<<cdiv(n, 128), 128, SMEM2>>>(agg, W2, h, dinv, n);
    aggregate_kernel<D2, false><<<cdiv(n, 8), 256>>>(rowptr, sorted, h, out, dinv, b2, n);
}

// round 9
// speedup vs baseline: 1.8007x; 1.0090x over previous
#include <cuda_runtime.h>
#include <cuda_bf16.h>
#include <cstdint>

// ---------------------------------------------------------------------------
// GCNEncoder: out = GCNConv2( relu( GCNConv1(x) ) )
// h = x@W (raw); agg[d] = sum_in dinv[s]*h[s] + dinv[d]*h[d];
// res = dinv[d]*agg + b  (==  D^-1/2 (A+I) D^-1/2 (x@W) + b)
// GEMM1 forked onto a second stream -> overlaps the CSR build in the graph.
// ---------------------------------------------------------------------------

#define NMAX 100000
#define EMAX 1600000
#define D0 128
#define D1 128
#define D2 64
#define SCAN_B 1024

#if defined(__CUDA_ARCH_FEAT_SM103_ALL) || defined(__CUDA_ARCH_FEAT_SM100_ALL) || \
    (defined(__CUDA_ARCH_SPECIFIC__) && (__CUDA_ARCH__ >= 1000))
#define HAS_TCGEN05 1
#else
#define HAS_TCGEN05 0
#endif

__device__ float g_dinv[NMAX];
__device__ float g_h[(size_t)NMAX * D1];
__device__ float g_agg[(size_t)NMAX * D1];
__device__ int   g_src[EMAX];
__device__ int   g_dst[EMAX];
__device__ int   g_rank[EMAX];
__device__ int   g_sorted[EMAX];
__device__ int   g_cnt[NMAX];
__device__ int   g_rowptr[NMAX + 1];
__device__ int   g_bsum[128];
__device__ int   g_bpre[128];
__device__ int   g_idx64;

// ---------------------------------------------------------------------------
// PTX helpers
// ---------------------------------------------------------------------------
__device__ __forceinline__ uint32_t smem_u32(const void* p) {
    uint32_t a;
    asm("{ .reg .u64 t; cvta.to.shared.u64 t, %1; cvt.u32.u64 %0, t; }"
        : "=r"(a) : "l"(p));
    return a;
}

#if HAS_TCGEN05
__device__ __forceinline__ uint32_t elect1() {
    uint32_t p;
    asm volatile("{ .reg .pred p; elect.sync _|p, 0xFFFFFFFF; selp.b32 %0,1,0,p; }"
                 : "=r"(p));
    return p;
}

#define TC_ALLOC(smem_addr, ncols) \
    asm volatile("tcgen05.alloc.cta_group::1.sync.aligned.shared::cta.b32 [%0], %1;" \
                 :: "r"(smem_addr), "r"(ncols) : "memory")
#define TC_DEALLOC(tmem, ncols) \
    asm volatile("tcgen05.dealloc.cta_group::1.sync.aligned.b32 %0, %1;" \
                 :: "r"(tmem), "r"(ncols))
#define TC_COMMIT(mbar) \
    asm volatile("tcgen05.commit.cta_group::1.mbarrier::arrive::one.shared::cluster.b64 [%0];" \
                 :: "r"(mbar) : "memory")
#define TC_WAIT_LD() asm volatile("tcgen05.wait::ld.sync.aligned;" ::: "memory")
#define TC_FENCE_AFTER() asm volatile("tcgen05.fence::after_thread_sync;" ::: "memory")
#define MBAR_INIT(mbar, cnt) \
    asm volatile("mbarrier.init.shared.b64 [%0], %1;" :: "r"(mbar), "r"(cnt) : "memory")

#define MBAR_WAIT(mbar, ph) do {                                              \
    uint32_t _done;                                                           \
    asm volatile("{\n\t.reg .pred p;\n\t"                                     \
        "mbarrier.try_wait.parity.acquire.cta.shared::cta.b64 p, [%1], %2;\n\t" \
        "selp.b32 %0,1,0,p;\n\t}"                                             \
        : "=r"(_done) : "r"(mbar), "r"(ph) : "memory");                       \
    if (!_done) {                                                             \
        asm volatile("{\n\t.reg .pred P1;\n\t"                                \
            "W1_%=:\n\t"                                                      \
            "mbarrier.try_wait.parity.acquire.cta.shared::cta.b64 P1, [%0], %1, 0x989680;\n\t" \
            "@P1 bra.uni W2_%=;\n\tbra.uni W1_%=;\n\tW2_%=:\n\t}"             \
            :: "r"(mbar), "r"(ph) : "memory");                                \
    }                                                                         \
} while (0)

#define TC_LD_X32(r, tmem)                                                    \
    asm volatile("tcgen05.ld.sync.aligned.32x32b.x32.b32 "                    \
        "{%0, %1, %2, %3, %4, %5, %6, %7, "                                   \
        " %8, %9, %10, %11, %12, %13, %14, %15, "                             \
        " %16, %17, %18, %19, %20, %21, %22, %23, "                           \
        " %24, %25, %26, %27, %28, %29, %30, %31}, [%32];"                    \
        : "=r"((r)[0]),  "=r"((r)[1]),  "=r"((r)[2]),  "=r"((r)[3]),          \
          "=r"((r)[4]),  "=r"((r)[5]),  "=r"((r)[6]),  "=r"((r)[7]),          \
          "=r"((r)[8]),  "=r"((r)[9]),  "=r"((r)[10]), "=r"((r)[11]),         \
          "=r"((r)[12]), "=r"((r)[13]), "=r"((r)[14]), "=r"((r)[15]),         \
          "=r"((r)[16]), "=r"((r)[17]), "=r"((r)[18]), "=r"((r)[19]),         \
          "=r"((r)[20]), "=r"((r)[21]), "=r"((r)[22]), "=r"((r)[23]),         \
          "=r"((r)[24]), "=r"((r)[25]), "=r"((r)[26]), "=r"((r)[27]),         \
          "=r"((r)[28]), "=r"((r)[29]), "=r"((r)[30]), "=r"((r)[31])          \
        : "r"(tmem))

__device__ __forceinline__ void mma_ss_f16(uint32_t d, uint64_t a, uint64_t b,
                                           uint32_t idesc, bool acc) {
    uint32_t e = acc ? 1u : 0u;
    asm volatile(
        "{\n\t.reg .pred p;\n\tsetp.ne.u32 p, %4, 0;\n\t"
        "tcgen05.mma.cta_group::1.kind::f16 [%0], %1, %2, %3, {%5,%5,%5,%5}, p;\n\t}"
        :: "r"(d), "l"(a), "l"(b), "r"(idesc), "r"(e), "r"(0u)
        : "memory");
}
#endif  // HAS_TCGEN05

// SW128 blocked-atom offset: atom = 8 rows x 64 bf16 (1024B), col-major atoms.
template <int ROWS>
__device__ __forceinline__ uint32_t sw_off(int r, int c) {
    uint32_t atom = (uint32_t)(r >> 3) + (uint32_t)(c >> 6) * (ROWS >> 3);
    uint32_t off = atom * 1024 + (r & 7) * 128 + (c & 63) * 2;
    return off ^ ((off >> 3) & 0x70);
}

__device__ __forceinline__ void split4(float4 v, unsigned long long& hi,
                                       unsigned long long& lo) {
    __nv_bfloat16 h0 = __float2bfloat16(v.x), h1 = __float2bfloat16(v.y);
    __nv_bfloat16 h2 = __float2bfloat16(v.z), h3 = __float2bfloat16(v.w);
    __nv_bfloat16 l0 = __float2bfloat16(v.x - __bfloat162float(h0));
    __nv_bfloat16 l1 = __float2bfloat16(v.y - __bfloat162float(h1));
    __nv_bfloat16 l2 = __float2bfloat16(v.z - __bfloat162float(h2));
    __nv_bfloat16 l3 = __float2bfloat16(v.w - __bfloat162float(h3));
    hi = (unsigned long long)__bfloat16_as_ushort(h0)
       | ((unsigned long long)__bfloat16_as_ushort(h1) << 16)
       | ((unsigned long long)__bfloat16_as_ushort(h2) << 32)
       | ((unsigned long long)__bfloat16_as_ushort(h3) << 48);
    lo = (unsigned long long)__bfloat16_as_ushort(l0)
       | ((unsigned long long)__bfloat16_as_ushort(l1) << 16)
       | ((unsigned long long)__bfloat16_as_ushort(l2) << 32)
       | ((unsigned long long)__bfloat16_as_ushort(l3) << 48);
}

// ---------------------------------------------------------------------------
// GEMM: C = A @ W  (no scaling -- dinv folded into aggregate now)
// ---------------------------------------------------------------------------
template <int OUT>
__global__ void __launch_bounds__(128) tc_gemm(
    const float* __restrict__ A, const float* __restrict__ W,
    float* __restrict__ C, int n)
{
    extern __shared__ char smem[];
    constexpr int K = 128;
    const int tid = threadIdx.x;
    const int row0 = blockIdx.x * 128;

#if HAS_TCGEN05
    constexpr uint32_t A_HI = 1024;
    constexpr uint32_t A_LO = A_HI + 128 * 256;
    constexpr uint32_t B_HI = A_LO + 128 * 256;
    constexpr uint32_t B_LO = B_HI + OUT * 256;

    const uint32_t sb = smem_u32(smem);
    const int wid = tid >> 5, lane = tid & 31;

    if (wid == 0) TC_ALLOC(sb + 0, 128);
    __syncthreads();
    uint32_t tmem;
    asm volatile("ld.shared.b32 %0, [%1];" : "=r"(tmem) : "r"(sb + 0));

    {
        int r = row0 + tid;
        if (r < n) {
            const float4* src = (const float4*)&A[(size_t)r * K];
#pragma unroll
            for (int c = 0; c < K; c += 4) {
                unsigned long long hi, lo;
                split4(src[c >> 2], hi, lo);
                uint32_t o = sw_off<128>(tid, c);
                *(unsigned long long*)(smem + A_HI + o) = hi;
                *(unsigned long long*)(smem + A_LO + o) = lo;
            }
        } else {
#pragma unroll
            for (int c = 0; c < K; c += 4) {
                uint32_t o = sw_off<128>(tid, c);
                *(unsigned long long*)(smem + A_HI + o) = 0ull;
                *(unsigned long long*)(smem + A_LO + o) = 0ull;
            }
        }
    }

    {
        int br, k0, kcnt;
        if (OUT == 128) { br = tid; k0 = 0; kcnt = K; }
        else { br = tid & (OUT - 1); k0 = (tid / OUT) * (K / (128 / OUT)); kcnt = K / (128 / OUT); }
#pragma unroll 4
        for (int k = k0; k < k0 + kcnt; k += 4) {
            float4 v = make_float4(W[(size_t)(k + 0) * OUT + br],
                                   W[(size_t)(k + 1) * OUT + br],
                                   W[(size_t)(k + 2) * OUT + br],
                                   W[(size_t)(k + 3) * OUT + br]);
            unsigned long long hi, lo;
            split4(v, hi, lo);
            uint32_t o = sw_off<OUT>(br, k);
            *(unsigned long long*)(smem + B_HI + o) = hi;
            *(unsigned long long*)(smem + B_LO + o) = lo;
        }
    }
    asm volatile("fence.proxy.async.shared::cta;" ::: "memory");
    __syncthreads();

    if (tid == 0) MBAR_INIT(sb + 8, 1);
    __syncthreads();

    if (wid == 0) {
        if (elect1()) {
            const uint64_t DB = (2ull << 61) | (1ull << 46) | (64ull << 32) | (1ull << 16);
            uint64_t dAhi = DB | (((sb + A_HI) >> 4) & 0x3FFF);
            uint64_t dAlo = DB | (((sb + A_LO) >> 4) & 0x3FFF);
            uint64_t dBhi = DB | (((sb + B_HI) >> 4) & 0x3FFF);
            uint64_t dBlo = DB | (((sb + B_LO) >> 4) & 0x3FFF);
            constexpr uint32_t idesc =
                (1u << 4) | (1u << 7) | (1u << 10) | ((OUT / 8) << 17) | (8u << 24);
            bool first = true;
#pragma unroll
            for (int s = 0; s < 8; s++) {
                uint64_t ao = (s < 4) ? (uint64_t)(s * 2) : (uint64_t)(1024 + (s - 4) * 2);
                uint64_t bo = (s < 4) ? (uint64_t)(s * 2) : (uint64_t)(OUT * 8 + (s - 4) * 2);
                mma_ss_f16(tmem, dAhi + ao, dBhi + bo, idesc, !first);
                first = false;
                mma_ss_f16(tmem, dAhi + ao, dBlo + bo, idesc, true);
                mma_ss_f16(tmem, dAlo + ao, dBhi + bo, idesc, true);
            }
            TC_COMMIT(sb + 8);
        }
    }

    MBAR_WAIT(sb + 8, 0);
    TC_FENCE_AFTER();

    {
        int r = row0 + wid * 32 + lane;
#pragma unroll
        for (int ch = 0; ch < OUT; ch += 32) {
            uint32_t rg[32];
            TC_LD_X32(rg, tmem + ch);
            TC_WAIT_LD();
            if (r < n) {
#pragma unroll
                for (int j = 0; j < 32; j += 4) {
                    float4 v = make_float4(__uint_as_float(rg[j + 0]),
                                           __uint_as_float(rg[j + 1]),
                                           __uint_as_float(rg[j + 2]),
                                           __uint_as_float(rg[j + 3]));
                    *(float4*)&C[(size_t)r * OUT + ch + j] = v;
                }
            }
        }
    }

    __syncthreads();
    if (wid == 0) {
        if (elect1())
            asm volatile("mbarrier.inval.shared.b64 [%0];" :: "r"(sb + 8) : "memory");
        TC_DEALLOC(tmem, 128);
    }

#else  // FFMA fallback (virtual-arch build)
    constexpr int NTX = OUT / 8;
    constexpr int NTY = 128 / NTX;
    constexpr int RPT = 64 / NTY;
    float* As = (float*)smem;
    float* Bs = (float*)(smem + 8 * 64 * 4);

    const int tx = tid % NTX;
    const int ty = tid / NTX;

    for (int half = 0; half < 2; half++) {
        const int rbase = row0 + half * 64;
        float acc[RPT][8];
#pragma unroll
        for (int i = 0; i < RPT; i++)
#pragma unroll
            for (int j = 0; j < 8; j++) acc[i][j] = 0.f;

        for (int k0 = 0; k0 < K; k0 += 8) {
            int ar = tid >> 1, ac = (tid & 1) << 2;
            float4 av = make_float4(0.f, 0.f, 0.f, 0.f);
            if (rbase + ar < n)
                av = *(const float4*)&A[(size_t)(rbase + ar) * K + k0 + ac];
            As[(ac + 0) * 64 + ar] = av.x;
            As[(ac + 1) * 64 + ar] = av.y;
            As[(ac + 2) * 64 + ar] = av.z;
            As[(ac + 3) * 64 + ar] = av.w;
#pragma unroll
            for (int i = tid; i < 8 * OUT; i += 128)
                Bs[i] = W[(size_t)(k0 + i / OUT) * OUT + (i % OUT)];
            __syncthreads();
#pragma unroll
            for (int k = 0; k < 8; k++) {
                float a[RPT], b[8];
#pragma unroll
                for (int i = 0; i < RPT; i++) a[i] = As[k * 64 + ty * RPT + i];
                *(float4*)&b[0] = *(float4*)&Bs[k * OUT + tx * 8];
                *(float4*)&b[4] = *(float4*)&Bs[k * OUT + tx * 8 + 4];
#pragma unroll
                for (int i = 0; i < RPT; i++)
#pragma unroll
                    for (int j = 0; j < 8; j++) acc[i][j] += a[i] * b[j];
            }
            __syncthreads();
        }

#pragma unroll
        for (int i = 0; i < RPT; i++) {
            int r = rbase + ty * RPT + i;
            if (r < n) {
                float4 v0 = make_float4(acc[i][0], acc[i][1], acc[i][2], acc[i][3]);
                float4 v1 = make_float4(acc[i][4], acc[i][5], acc[i][6], acc[i][7]);
                *(float4*)&C[(size_t)r * OUT + tx * 8] = v0;
                *(float4*)&C[(size_t)r * OUT + tx * 8 + 4] = v1;
            }
        }
        __syncthreads();
    }
#endif
}

// ---------------------------------------------------------------------------
// CSR build, pass 1: decode (dtype-robust) + histogram + per-edge rank
// ---------------------------------------------------------------------------
__global__ void probe_kernel(const int* __restrict__ w, int nwords) {
    if (threadIdx.x == 0 && blockIdx.x == 0) {
        int limit = nwords < 2048 ? nwords : 2048;
        int acc = 0;
        for (int i = 1; i < limit; i += 2) acc |= w[i];
        g_idx64 = (acc == 0) ? 1 : 0;
    }
}

__global__ void decode_hist_kernel(const int* __restrict__ w, int* cnt,
                                   int E, int n) {
    int e = blockIdx.x * blockDim.x + threadIdx.x;
    if (e >= E) return;
    int s, d;
    if (g_idx64) {
        s = w[2 * (size_t)e];
        d = w[2 * ((size_t)E + e)];
    } else {
        s = w[e];
        d = w[(size_t)E + e];
    }
    if ((unsigned)s >= (unsigned)n) s = 0;
    if ((unsigned)d >= (unsigned)n) d = 0;
    g_src[e] = s;
    g_dst[e] = d;
    g_rank[e] = atomicAdd(&cnt[d], 1);
}

// ---------------------------------------------------------------------------
// scan: per-block sums -> parallel block-prefix -> full scan (+dinv)
// ---------------------------------------------------------------------------
__global__ void scan1_kernel(const int* __restrict__ cnt, int* bsum, int n) {
    __shared__ int s[SCAN_B];
    int i = blockIdx.x * SCAN_B + threadIdx.x;
    s[threadIdx.x] = (i < n) ? cnt[i] : 0;
    __syncthreads();
    for (int off = SCAN_B / 2; off > 0; off >>= 1) {
        if (threadIdx.x < off) s[threadIdx.x] += s[threadIdx.x + off];
        __syncthreads();
    }
    if (threadIdx.x == 0) bsum[blockIdx.x] = s[0];
}

__global__ void scan2_kernel(const int* __restrict__ bsum, int* bpre,
                             int* rowptr, int nb, int n) {
    __shared__ int s[128];
    int t = threadIdx.x;
    int v = (t < nb) ? bsum[t] : 0;
    s[t] = v;
    __syncthreads();
    for (int off = 1; off < 128; off <<= 1) {
        int u = (t >= off) ? s[t - off] : 0;
        __syncthreads();
        s[t] += u;
        __syncthreads();
    }
    if (t < nb) bpre[t] = s[t] - v;
    if (t == 127) rowptr[n] = s[127];
}

__global__ void scan3_kernel(const int* __restrict__ cnt,
                             const int* __restrict__ bpre,
                             int* rowptr, float* dinv, int n) {
    __shared__ int s[SCAN_B];
    int i = blockIdx.x * SCAN_B + threadIdx.x;
    int v = (i < n) ? cnt[i] : 0;
    s[threadIdx.x] = v;
    __syncthreads();
    for (int off = 1; off < SCAN_B; off <<= 1) {
        int t = (threadIdx.x >= off) ? s[threadIdx.x - off] : 0;
        __syncthreads();
        s[threadIdx.x] += t;
        __syncthreads();
    }
    if (i < n) {
        rowptr[i] = s[threadIdx.x] - v + bpre[blockIdx.x];
        dinv[i] = rsqrtf(1.0f + (float)v);  // +1 self-loop
    }
}

// ---------------------------------------------------------------------------
// CSR build, pass 2: atomic-free scatter using precomputed ranks
// ---------------------------------------------------------------------------
__global__ void scatter_sort_kernel(const int* __restrict__ src,
                                    const int* __restrict__ dst,
                                    const int* __restrict__ rank,
                                    const int* __restrict__ rowptr,
                                    int* sorted, int E) {
    int e = blockIdx.x * blockDim.x + threadIdx.x;
    if (e >= E) return;
    sorted[rowptr[dst[e]] + rank[e]] = src[e];
}

// ---------------------------------------------------------------------------
// Fused aggregate: res[d] = f( dinv[d]*( sum_in dinv[s]*h[s] + dinv[d]*h[d] ) + b )
// One warp per dst node; dinv applied per-source (h is unscaled).
// ---------------------------------------------------------------------------
template <int DIM, bool RELU>
__global__ void __launch_bounds__(256) aggregate_kernel(
    const int* __restrict__ rowptr, const int* __restrict__ sorted,
    const float* __restrict__ h, float* __restrict__ res,
    const float* __restrict__ dinv, const float* __restrict__ bias, int n)
{
    constexpr int VPL = DIM / 32;  // floats per lane: 4 (D=128) or 2 (D=64)
    int node = (int)((blockIdx.x * (long long)blockDim.x + threadIdx.x) >> 5);
    int lane = threadIdx.x & 31;
    if (node >= n) return;

    const int beg = rowptr[node];
    const int end = rowptr[node + 1];
    const int col = lane * VPL;
    const float di = dinv[node];

    float acc[VPL];
    // self-loop init: di * h[node]  (outer di applied in epilogue -> di^2 total)
    if (VPL == 4) {
        float4 v = *(const float4*)&h[(size_t)node * DIM + col];
        acc[0] = di * v.x; acc[1] = di * v.y; acc[2] = di * v.z; acc[3] = di * v.w;
    } else {
        float2 v = *(const float2*)&h[(size_t)node * DIM + col];
        acc[0] = di * v.x; acc[1] = di * v.y;
    }

    int e = beg;
    for (; e + 4 <= end; e += 4) {
        int s0 = sorted[e + 0], s1 = sorted[e + 1];
        int s2 = sorted[e + 2], s3 = sorted[e + 3];
        float w0 = dinv[s0], w1 = dinv[s1], w2 = dinv[s2], w3 = dinv[s3];
        if (VPL == 4) {
            float4 v0 = *(const float4*)&h[(size_t)s0 * DIM + col];
            float4 v1 = *(const float4*)&h[(size_t)s1 * DIM + col];
            float4 v2 = *(const float4*)&h[(size_t)s2 * DIM + col];
            float4 v3 = *(const float4*)&h[(size_t)s3 * DIM + col];
            acc[0] += (w0 * v0.x + w1 * v1.x) + (w2 * v2.x + w3 * v3.x);
            acc[1] += (w0 * v0.y + w1 * v1.y) + (w2 * v2.y + w3 * v3.y);
            acc[2] += (w0 * v0.z + w1 * v1.z) + (w2 * v2.z + w3 * v3.z);
            acc[3] += (w0 * v0.w + w1 * v1.w) + (w2 * v2.w + w3 * v3.w);
        } else {
            float2 v0 = *(const float2*)&h[(size_t)s0 * DIM + col];
            float2 v1 = *(const float2*)&h[(size_t)s1 * DIM + col];
            float2 v2 = *(const float2*)&h[(size_t)s2 * DIM + col];
            float2 v3 = *(const float2*)&h[(size_t)s3 * DIM + col];
            acc[0] += (w0 * v0.x + w1 * v1.x) + (w2 * v2.x + w3 * v3.x);
            acc[1] += (w0 * v0.y + w1 * v1.y) + (w2 * v2.y + w3 * v3.y);
        }
    }
    for (; e < end; e++) {
        int s = sorted[e];
        float w = dinv[s];
        if (VPL == 4) {
            float4 v = *(const float4*)&h[(size_t)s * DIM + col];
            acc[0] += w * v.x; acc[1] += w * v.y;
            acc[2] += w * v.z; acc[3] += w * v.w;
        } else {
            float2 v = *(const float2*)&h[(size_t)s * DIM + col];
            acc[0] += w * v.x; acc[1] += w * v.y;
        }
    }

    if (VPL == 4) {
        float4 b = *(const float4*)&bias[col];
        float4 r;
        r.x = di * acc[0] + b.x;
        r.y = di * acc[1] + b.y;
        r.z = di * acc[2] + b.z;
        r.w = di * acc[3] + b.w;
        if (RELU) {
            r.x = fmaxf(r.x, 0.f); r.y = fmaxf(r.y, 0.f);
            r.z = fmaxf(r.z, 0.f); r.w = fmaxf(r.w, 0.f);
        }
        *(float4*)&res[(size_t)node * DIM + col] = r;
    } else {
        float2 b = *(const float2*)&bias[col];
        float2 r;
        r.x = di * acc[0] + b.x;
        r.y = di * acc[1] + b.y;
        if (RELU) { r.x = fmaxf(r.x, 0.f); r.y = fmaxf(r.y, 0.f); }
        *(float2*)&res[(size_t)node * DIM + col] = r;
    }
}

// ---------------------------------------------------------------------------
// launch
// ---------------------------------------------------------------------------
static inline int cdiv(long long a, long long b) { return (int)((a + b - 1) / b); }

extern "C" void kernel_launch(void* const* d_in, const int* in_sizes, int n_in,
                              void* d_out, int out_size)
{
    const float* x   = (const float*)d_in[0];
    const int*   eiw = (const int*)d_in[1];
    const float* W1  = (const float*)d_in[2];
    const float* b1  = (const float*)d_in[3];
    const float* W2  = (const float*)d_in[4];
    const float* b2  = (const float*)d_in[5];
    float*       out = (float*)d_out;

    const int n = in_sizes[0] / D0;
    int E = in_sizes[1] / 2;
    if (E > EMAX) E = EMAX;
    const int NB = cdiv(n, SCAN_B);

    float *dinv, *h, *agg;
    int *srcp, *dstp, *rankp, *sorted, *cnt, *rowptr, *bsum, *bpre;
    cudaGetSymbolAddress((void**)&dinv,   g_dinv);
    cudaGetSymbolAddress((void**)&h,      g_h);
    cudaGetSymbolAddress((void**)&agg,    g_agg);
    cudaGetSymbolAddress((void**)&srcp,   g_src);
    cudaGetSymbolAddress((void**)&dstp,   g_dst);
    cudaGetSymbolAddress((void**)&rankp,  g_rank);
    cudaGetSymbolAddress((void**)&sorted, g_sorted);
    cudaGetSymbolAddress((void**)&cnt,    g_cnt);
    cudaGetSymbolAddress((void**)&rowptr, g_rowptr);
    cudaGetSymbolAddress((void**)&bsum,   g_bsum);
    cudaGetSymbolAddress((void**)&bpre,   g_bpre);

    constexpr int SMEM1 = 1024 + 2 * 128 * 256 + 2 * 128 * 256;
    constexpr int SMEM2 = 1024 + 2 * 128 * 256 + 2 * 64 * 256;
    cudaFuncSetAttribute(tc_gemm<128>, cudaFuncAttributeMaxDynamicSharedMemorySize, SMEM1);
    cudaFuncSetAttribute(tc_gemm<64>,  cudaFuncAttributeMaxDynamicSharedMemorySize, SMEM2);

    // fork/join resources (leaked deliberately: kernel_launch is called only a
    // couple of times; no device memory is allocated by these objects' use here)
    cudaStream_t s2;
    cudaStreamCreateWithFlags(&s2, cudaStreamNonBlocking);
    cudaEvent_t evRoot, evGemm;
    cudaEventCreateWithFlags(&evRoot, cudaEventDisableTiming);
    cudaEventCreateWithFlags(&evGemm, cudaEventDisableTiming);

    // --- fork: gemm1 (independent of CSR/dinv now) on side stream ---
    cudaEventRecord(evRoot, 0);
    cudaStreamWaitEvent(s2, evRoot, 0);
    tc_gemm<D1><<<cdiv(n, 128), 128, SMEM1, s2>>>(x, W1, h, n);
    cudaEventRecord(evGemm, s2);

    // --- CSR build on main stream (concurrent with gemm1) ---
    probe_kernel<<<1, 32>>>(eiw, in_sizes[1]);
    cudaMemsetAsync(cnt, 0, (size_t)n * sizeof(int));
    decode_hist_kernel<<<cdiv(E, 256), 256>>>(eiw, cnt, E, n);
    scan1_kernel<<<NB, SCAN_B>>>(cnt, bsum, n);
    scan2_kernel<<<1, 128>>>(bsum, bpre, rowptr, NB, n);
    scan3_kernel<<<NB, SCAN_B>>>(cnt, bpre, rowptr, dinv, n);
    scatter_sort_kernel<<<cdiv(E, 256), 256>>>(srcp, dstp, rankp, rowptr, sorted, E);

    // --- join, then layer 1 aggregate ---
    cudaStreamWaitEvent(0, evGemm, 0);
    aggregate_kernel<D1, true><<<cdiv(n, 8), 256>>>(rowptr, sorted, h, agg, dinv, b1, n);

    // --- layer 2 ---
    tc_gemm<D2><<<cdiv(n, 128), 128, SMEM2>>>(agg, W2, h, n);
    aggregate_kernel<D2, false><<<cdiv(n, 8), 256>>>(rowptr, sorted, h, out, dinv, b2, n);
}

// round 13
// speedup vs baseline: 1.8167x; 1.0089x over previous
#include <cuda_runtime.h>
#include <cuda_bf16.h>
#include <cstdint>

// ---------------------------------------------------------------------------
// GCNEncoder: out = GCNConv2( relu( GCNConv1(x) ) )
// Prescale: h_s = (x@W)*dinv ; agg[d] = sum_in h_s[src] + h_s[d] ;
// res = dinv[d]*agg + b  (==  D^-1/2 (A+I) D^-1/2 (x@W) + b)
// CSR: decode+hist+rank -> order-free segment assign (atomic cursor, scan-free)
//      -> atomic-free bucket scatter.  Aggregate: warp-per-node gather.
// GEMMs: tcgen05 bf16 hi/lo split (sm_103a) / FFMA fallback (compute_103).
// ---------------------------------------------------------------------------

#define NMAX 100000
#define EMAX 1600000
#define D0 128
#define D1 128
#define D2 64

#if defined(__CUDA_ARCH_FEAT_SM103_ALL) || defined(__CUDA_ARCH_FEAT_SM100_ALL) || \
    (defined(__CUDA_ARCH_SPECIFIC__) && (__CUDA_ARCH__ >= 1000))
#define HAS_TCGEN05 1
#else
#define HAS_TCGEN05 0
#endif

__device__ float g_dinv[NMAX];
__device__ float g_h[(size_t)NMAX * D1];
__device__ float g_agg[(size_t)NMAX * D1];
__device__ int   g_src[EMAX];
__device__ int   g_dst[EMAX];
__device__ int   g_rank[EMAX];
__device__ int   g_sorted[EMAX];
__device__ int   g_cnt[NMAX];
__device__ int   g_rowptr[NMAX];
__device__ int   g_cursor;
__device__ int   g_idx64;

// ---------------------------------------------------------------------------
// PTX helpers
// ---------------------------------------------------------------------------
__device__ __forceinline__ uint32_t smem_u32(const void* p) {
    uint32_t a;
    asm("{ .reg .u64 t; cvta.to.shared.u64 t, %1; cvt.u32.u64 %0, t; }"
        : "=r"(a) : "l"(p));
    return a;
}

#if HAS_TCGEN05
__device__ __forceinline__ uint32_t elect1() {
    uint32_t p;
    asm volatile("{ .reg .pred p; elect.sync _|p, 0xFFFFFFFF; selp.b32 %0,1,0,p; }"
                 : "=r"(p));
    return p;
}

#define TC_ALLOC(smem_addr, ncols) \
    asm volatile("tcgen05.alloc.cta_group::1.sync.aligned.shared::cta.b32 [%0], %1;" \
                 :: "r"(smem_addr), "r"(ncols) : "memory")
#define TC_DEALLOC(tmem, ncols) \
    asm volatile("tcgen05.dealloc.cta_group::1.sync.aligned.b32 %0, %1;" \
                 :: "r"(tmem), "r"(ncols))
#define TC_COMMIT(mbar) \
    asm volatile("tcgen05.commit.cta_group::1.mbarrier::arrive::one.shared::cluster.b64 [%0];" \
                 :: "r"(mbar) : "memory")
#define TC_WAIT_LD() asm volatile("tcgen05.wait::ld.sync.aligned;" ::: "memory")
#define TC_FENCE_AFTER() asm volatile("tcgen05.fence::after_thread_sync;" ::: "memory")
#define MBAR_INIT(mbar, cnt) \
    asm volatile("mbarrier.init.shared.b64 [%0], %1;" :: "r"(mbar), "r"(cnt) : "memory")

#define MBAR_WAIT(mbar, ph) do {                                              \
    uint32_t _done;                                                           \
    asm volatile("{\n\t.reg .pred p;\n\t"                                     \
        "mbarrier.try_wait.parity.acquire.cta.shared::cta.b64 p, [%1], %2;\n\t" \
        "selp.b32 %0,1,0,p;\n\t}"                                             \
        : "=r"(_done) : "r"(mbar), "r"(ph) : "memory");                       \
    if (!_done) {                                                             \
        asm volatile("{\n\t.reg .pred P1;\n\t"                                \
            "W1_%=:\n\t"                                                      \
            "mbarrier.try_wait.parity.acquire.cta.shared::cta.b64 P1, [%0], %1, 0x989680;\n\t" \
            "@P1 bra.uni W2_%=;\n\tbra.uni W1_%=;\n\tW2_%=:\n\t}"             \
            :: "r"(mbar), "r"(ph) : "memory");                                \
    }                                                                         \
} while (0)

#define TC_LD_X32(r, tmem)                                                    \
    asm volatile("tcgen05.ld.sync.aligned.32x32b.x32.b32 "                    \
        "{%0, %1, %2, %3, %4, %5, %6, %7, "                                   \
        " %8, %9, %10, %11, %12, %13, %14, %15, "                             \
        " %16, %17, %18, %19, %20, %21, %22, %23, "                           \
        " %24, %25, %26, %27, %28, %29, %30, %31}, [%32];"                    \
        : "=r"((r)[0]),  "=r"((r)[1]),  "=r"((r)[2]),  "=r"((r)[3]),          \
          "=r"((r)[4]),  "=r"((r)[5]),  "=r"((r)[6]),  "=r"((r)[7]),          \
          "=r"((r)[8]),  "=r"((r)[9]),  "=r"((r)[10]), "=r"((r)[11]),         \
          "=r"((r)[12]), "=r"((r)[13]), "=r"((r)[14]), "=r"((r)[15]),         \
          "=r"((r)[16]), "=r"((r)[17]), "=r"((r)[18]), "=r"((r)[19]),         \
          "=r"((r)[20]), "=r"((r)[21]), "=r"((r)[22]), "=r"((r)[23]),         \
          "=r"((r)[24]), "=r"((r)[25]), "=r"((r)[26]), "=r"((r)[27]),         \
          "=r"((r)[28]), "=r"((r)[29]), "=r"((r)[30]), "=r"((r)[31])          \
        : "r"(tmem))

__device__ __forceinline__ void mma_ss_f16(uint32_t d, uint64_t a, uint64_t b,
                                           uint32_t idesc, bool acc) {
    uint32_t e = acc ? 1u : 0u;
    asm volatile(
        "{\n\t.reg .pred p;\n\tsetp.ne.u32 p, %4, 0;\n\t"
        "tcgen05.mma.cta_group::1.kind::f16 [%0], %1, %2, %3, {%5,%5,%5,%5}, p;\n\t}"
        :: "r"(d), "l"(a), "l"(b), "r"(idesc), "r"(e), "r"(0u)
        : "memory");
}
#endif  // HAS_TCGEN05

// SW128 blocked-atom offset: atom = 8 rows x 64 bf16 (1024B), col-major atoms.
template <int ROWS>
__device__ __forceinline__ uint32_t sw_off(int r, int c) {
    uint32_t atom = (uint32_t)(r >> 3) + (uint32_t)(c >> 6) * (ROWS >> 3);
    uint32_t off = atom * 1024 + (r & 7) * 128 + (c & 63) * 2;
    return off ^ ((off >> 3) & 0x70);
}

__device__ __forceinline__ void split4(float4 v, unsigned long long& hi,
                                       unsigned long long& lo) {
    __nv_bfloat16 h0 = __float2bfloat16(v.x), h1 = __float2bfloat16(v.y);
    __nv_bfloat16 h2 = __float2bfloat16(v.z), h3 = __float2bfloat16(v.w);
    __nv_bfloat16 l0 = __float2bfloat16(v.x - __bfloat162float(h0));
    __nv_bfloat16 l1 = __float2bfloat16(v.y - __bfloat162float(h1));
    __nv_bfloat16 l2 = __float2bfloat16(v.z - __bfloat162float(h2));
    __nv_bfloat16 l3 = __float2bfloat16(v.w - __bfloat162float(h3));
    hi = (unsigned long long)__bfloat16_as_ushort(h0)
       | ((unsigned long long)__bfloat16_as_ushort(h1) << 16)
       | ((unsigned long long)__bfloat16_as_ushort(h2) << 32)
       | ((unsigned long long)__bfloat16_as_ushort(h3) << 48);
    lo = (unsigned long long)__bfloat16_as_ushort(l0)
       | ((unsigned long long)__bfloat16_as_ushort(l1) << 16)
       | ((unsigned long long)__bfloat16_as_ushort(l2) << 32)
       | ((unsigned long long)__bfloat16_as_ushort(l3) << 48);
}

// ---------------------------------------------------------------------------
// GEMM: C[r,:] = dinv[r] * (A[r,:] @ W)
// ---------------------------------------------------------------------------
template <int OUT>
__global__ void __launch_bounds__(128) tc_gemm(
    const float* __restrict__ A, const float* __restrict__ W,
    float* __restrict__ C, const float* __restrict__ dinv, int n)
{
    extern __shared__ char smem[];
    constexpr int K = 128;
    const int tid = threadIdx.x;
    const int row0 = blockIdx.x * 128;

#if HAS_TCGEN05
    constexpr uint32_t A_HI = 1024;
    constexpr uint32_t A_LO = A_HI + 128 * 256;
    constexpr uint32_t B_HI = A_LO + 128 * 256;
    constexpr uint32_t B_LO = B_HI + OUT * 256;

    const uint32_t sb = smem_u32(smem);
    const int wid = tid >> 5, lane = tid & 31;

    if (wid == 0) TC_ALLOC(sb + 0, 128);
    __syncthreads();
    uint32_t tmem;
    asm volatile("ld.shared.b32 %0, [%1];" : "=r"(tmem) : "r"(sb + 0));

    {
        int r = row0 + tid;
        if (r < n) {
            const float4* src = (const float4*)&A[(size_t)r * K];
#pragma unroll
            for (int c = 0; c < K; c += 4) {
                unsigned long long hi, lo;
                split4(src[c >> 2], hi, lo);
                uint32_t o = sw_off<128>(tid, c);
                *(unsigned long long*)(smem + A_HI + o) = hi;
                *(unsigned long long*)(smem + A_LO + o) = lo;
            }
        } else {
#pragma unroll
            for (int c = 0; c < K; c += 4) {
                uint32_t o = sw_off<128>(tid, c);
                *(unsigned long long*)(smem + A_HI + o) = 0ull;
                *(unsigned long long*)(smem + A_LO + o) = 0ull;
            }
        }
    }

    {
        int br, k0, kcnt;
        if (OUT == 128) { br = tid; k0 = 0; kcnt = K; }
        else { br = tid & (OUT - 1); k0 = (tid / OUT) * (K / (128 / OUT)); kcnt = K / (128 / OUT); }
#pragma unroll 4
        for (int k = k0; k < k0 + kcnt; k += 4) {
            float4 v = make_float4(W[(size_t)(k + 0) * OUT + br],
                                   W[(size_t)(k + 1) * OUT + br],
                                   W[(size_t)(k + 2) * OUT + br],
                                   W[(size_t)(k + 3) * OUT + br]);
            unsigned long long hi, lo;
            split4(v, hi, lo);
            uint32_t o = sw_off<OUT>(br, k);
            *(unsigned long long*)(smem + B_HI + o) = hi;
            *(unsigned long long*)(smem + B_LO + o) = lo;
        }
    }
    asm volatile("fence.proxy.async.shared::cta;" ::: "memory");
    __syncthreads();

    if (tid == 0) MBAR_INIT(sb + 8, 1);
    __syncthreads();

    if (wid == 0) {
        if (elect1()) {
            const uint64_t DB = (2ull << 61) | (1ull << 46) | (64ull << 32) | (1ull << 16);
            uint64_t dAhi = DB | (((sb + A_HI) >> 4) & 0x3FFF);
            uint64_t dAlo = DB | (((sb + A_LO) >> 4) & 0x3FFF);
            uint64_t dBhi = DB | (((sb + B_HI) >> 4) & 0x3FFF);
            uint64_t dBlo = DB | (((sb + B_LO) >> 4) & 0x3FFF);
            constexpr uint32_t idesc =
                (1u << 4) | (1u << 7) | (1u << 10) | ((OUT / 8) << 17) | (8u << 24);
            bool first = true;
#pragma unroll
            for (int s = 0; s < 8; s++) {
                uint64_t ao = (s < 4) ? (uint64_t)(s * 2) : (uint64_t)(1024 + (s - 4) * 2);
                uint64_t bo = (s < 4) ? (uint64_t)(s * 2) : (uint64_t)(OUT * 8 + (s - 4) * 2);
                mma_ss_f16(tmem, dAhi + ao, dBhi + bo, idesc, !first);
                first = false;
                mma_ss_f16(tmem, dAhi + ao, dBlo + bo, idesc, true);
                mma_ss_f16(tmem, dAlo + ao, dBhi + bo, idesc, true);
            }
            TC_COMMIT(sb + 8);
        }
    }

    MBAR_WAIT(sb + 8, 0);
    TC_FENCE_AFTER();

    {
        int r = row0 + wid * 32 + lane;
        float sc = (r < n) ? dinv[r] : 0.f;
#pragma unroll
        for (int ch = 0; ch < OUT; ch += 32) {
            uint32_t rg[32];
            TC_LD_X32(rg, tmem + ch);
            TC_WAIT_LD();
            if (r < n) {
#pragma unroll
                for (int j = 0; j < 32; j += 4) {
                    float4 v = make_float4(__uint_as_float(rg[j + 0]) * sc,
                                           __uint_as_float(rg[j + 1]) * sc,
                                           __uint_as_float(rg[j + 2]) * sc,
                                           __uint_as_float(rg[j + 3]) * sc);
                    *(float4*)&C[(size_t)r * OUT + ch + j] = v;
                }
            }
        }
    }

    __syncthreads();
    if (wid == 0) {
        if (elect1())
            asm volatile("mbarrier.inval.shared.b64 [%0];" :: "r"(sb + 8) : "memory");
        TC_DEALLOC(tmem, 128);
    }

#else  // FFMA fallback (virtual-arch build)
    constexpr int NTX = OUT / 8;
    constexpr int NTY = 128 / NTX;
    constexpr int RPT = 64 / NTY;
    float* As = (float*)smem;
    float* Bs = (float*)(smem + 8 * 64 * 4);

    const int tx = tid % NTX;
    const int ty = tid / NTX;

    for (int half = 0; half < 2; half++) {
        const int rbase = row0 + half * 64;
        float acc[RPT][8];
#pragma unroll
        for (int i = 0; i < RPT; i++)
#pragma unroll
            for (int j = 0; j < 8; j++) acc[i][j] = 0.f;

        for (int k0 = 0; k0 < K; k0 += 8) {
            int ar = tid >> 1, ac = (tid & 1) << 2;
            float4 av = make_float4(0.f, 0.f, 0.f, 0.f);
            if (rbase + ar < n)
                av = *(const float4*)&A[(size_t)(rbase + ar) * K + k0 + ac];
            As[(ac + 0) * 64 + ar] = av.x;
            As[(ac + 1) * 64 + ar] = av.y;
            As[(ac + 2) * 64 + ar] = av.z;
            As[(ac + 3) * 64 + ar] = av.w;
#pragma unroll
            for (int i = tid; i < 8 * OUT; i += 128)
                Bs[i] = W[(size_t)(k0 + i / OUT) * OUT + (i % OUT)];
            __syncthreads();
#pragma unroll
            for (int k = 0; k < 8; k++) {
                float a[RPT], b[8];
#pragma unroll
                for (int i = 0; i < RPT; i++) a[i] = As[k * 64 + ty * RPT + i];
                *(float4*)&b[0] = *(float4*)&Bs[k * OUT + tx * 8];
                *(float4*)&b[4] = *(float4*)&Bs[k * OUT + tx * 8 + 4];
#pragma unroll
                for (int i = 0; i < RPT; i++)
#pragma unroll
                    for (int j = 0; j < 8; j++) acc[i][j] += a[i] * b[j];
            }
            __syncthreads();
        }

#pragma unroll
        for (int i = 0; i < RPT; i++) {
            int r = rbase + ty * RPT + i;
            if (r < n) {
                float sc = dinv[r];
                float4 v0 = make_float4(acc[i][0] * sc, acc[i][1] * sc,
                                        acc[i][2] * sc, acc[i][3] * sc);
                float4 v1 = make_float4(acc[i][4] * sc, acc[i][5] * sc,
                                        acc[i][6] * sc, acc[i][7] * sc);
                *(float4*)&C[(size_t)r * OUT + tx * 8] = v0;
                *(float4*)&C[(size_t)r * OUT + tx * 8 + 4] = v1;
            }
        }
        __syncthreads();
    }
#endif
}

// ---------------------------------------------------------------------------
// CSR build
// ---------------------------------------------------------------------------
__global__ void probe_kernel(const int* __restrict__ w, int nwords) {
    if (threadIdx.x == 0 && blockIdx.x == 0) {
        int limit = nwords < 2048 ? nwords : 2048;
        int acc = 0;
        for (int i = 1; i < limit; i += 2) acc |= w[i];
        g_idx64 = (acc == 0) ? 1 : 0;
        g_cursor = 0;
    }
}

__global__ void decode_hist_kernel(const int* __restrict__ w, int* cnt,
                                   int E, int n) {
    int e = blockIdx.x * blockDim.x + threadIdx.x;
    if (e >= E) return;
    int s, d;
    if (g_idx64) {
        s = w[2 * (size_t)e];
        d = w[2 * ((size_t)E + e)];
    } else {
        s = w[e];
        d = w[(size_t)E + e];
    }
    if ((unsigned)s >= (unsigned)n) s = 0;
    if ((unsigned)d >= (unsigned)n) d = 0;
    g_src[e] = s;
    g_dst[e] = d;
    g_rank[e] = atomicAdd(&cnt[d], 1);
}

// Order-free segment assignment (replaces the 3-kernel prefix scan) + dinv.
__global__ void assign_kernel(const int* __restrict__ cnt, int* rowptr,
                              float* dinv, int n) {
    int i = blockIdx.x * blockDim.x + threadIdx.x;
    if (i >= n) return;
    int c = cnt[i];
    rowptr[i] = (c > 0) ? atomicAdd(&g_cursor, c) : 0;
    dinv[i] = rsqrtf(1.0f + (float)c);  // +1 self-loop
}

__global__ void scatter_sort_kernel(const int* __restrict__ src,
                                    const int* __restrict__ dst,
                                    const int* __restrict__ rank,
                                    const int* __restrict__ rowptr,
                                    int* sorted, int E) {
    int e = blockIdx.x * blockDim.x + threadIdx.x;
    if (e >= E) return;
    sorted[rowptr[dst[e]] + rank[e]] = src[e];
}

// ---------------------------------------------------------------------------
// Fused aggregate: res[d] = f( dinv[d] * (sum_in h[src] + h[d]) + bias )
// (h is the dinv-prescaled transform output.)  One warp per dst node.
// ---------------------------------------------------------------------------
template <int DIM, bool RELU>
__global__ void __launch_bounds__(256) aggregate_kernel(
    const int* __restrict__ rowptr, const int* __restrict__ cnt,
    const int* __restrict__ sorted,
    const float* __restrict__ h, float* __restrict__ res,
    const float* __restrict__ dinv, const float* __restrict__ bias, int n)
{
    constexpr int VPL = DIM / 32;  // floats per lane: 4 (D=128) or 2 (D=64)
    int node = (int)((blockIdx.x * (long long)blockDim.x + threadIdx.x) >> 5);
    int lane = threadIdx.x & 31;
    if (node >= n) return;

    const int beg = rowptr[node];
    const int end = beg + cnt[node];
    const int col = lane * VPL;

    float acc[VPL];
    if (VPL == 4) {
        float4 v = *(const float4*)&h[(size_t)node * DIM + col];
        acc[0] = v.x; acc[1] = v.y; acc[2] = v.z; acc[3] = v.w;
    } else {
        float2 v = *(const float2*)&h[(size_t)node * DIM + col];
        acc[0] = v.x; acc[1] = v.y;
    }

    int e = beg;
    for (; e + 4 <= end; e += 4) {
        int s0 = sorted[e + 0], s1 = sorted[e + 1];
        int s2 = sorted[e + 2], s3 = sorted[e + 3];
        if (VPL == 4) {
            float4 v0 = *(const float4*)&h[(size_t)s0 * DIM + col];
            float4 v1 = *(const float4*)&h[(size_t)s1 * DIM + col];
            float4 v2 = *(const float4*)&h[(size_t)s2 * DIM + col];
            float4 v3 = *(const float4*)&h[(size_t)s3 * DIM + col];
            acc[0] += (v0.x + v1.x) + (v2.x + v3.x);
            acc[1] += (v0.y + v1.y) + (v2.y + v3.y);
            acc[2] += (v0.z + v1.z) + (v2.z + v3.z);
            acc[3] += (v0.w + v1.w) + (v2.w + v3.w);
        } else {
            float2 v0 = *(const float2*)&h[(size_t)s0 * DIM + col];
            float2 v1 = *(const float2*)&h[(size_t)s1 * DIM + col];
            float2 v2 = *(const float2*)&h[(size_t)s2 * DIM + col];
            float2 v3 = *(const float2*)&h[(size_t)s3 * DIM + col];
            acc[0] += (v0.x + v1.x) + (v2.x + v3.x);
            acc[1] += (v0.y + v1.y) + (v2.y + v3.y);
        }
    }
    for (; e < end; e++) {
        int s = sorted[e];
        if (VPL == 4) {
            float4 v = *(const float4*)&h[(size_t)s * DIM + col];
            acc[0] += v.x; acc[1] += v.y; acc[2] += v.z; acc[3] += v.w;
        } else {
            float2 v = *(const float2*)&h[(size_t)s * DIM + col];
            acc[0] += v.x; acc[1] += v.y;
        }
    }

    float di = dinv[node];
    if (VPL == 4) {
        float4 b = *(const float4*)&bias[col];
        float4 r;
        r.x = di * acc[0] + b.x;
        r.y = di * acc[1] + b.y;
        r.z = di * acc[2] + b.z;
        r.w = di * acc[3] + b.w;
        if (RELU) {
            r.x = fmaxf(r.x, 0.f); r.y = fmaxf(r.y, 0.f);
            r.z = fmaxf(r.z, 0.f); r.w = fmaxf(r.w, 0.f);
        }
        *(float4*)&res[(size_t)node * DIM + col] = r;
    } else {
        float2 b = *(const float2*)&bias[col];
        float2 r;
        r.x = di * acc[0] + b.x;
        r.y = di * acc[1] + b.y;
        if (RELU) { r.x = fmaxf(r.x, 0.f); r.y = fmaxf(r.y, 0.f); }
        *(float2*)&res[(size_t)node * DIM + col] = r;
    }
}

// ---------------------------------------------------------------------------
// launch
// ---------------------------------------------------------------------------
static inline int cdiv(long long a, long long b) { return (int)((a + b - 1) / b); }

extern "C" void kernel_launch(void* const* d_in, const int* in_sizes, int n_in,
                              void* d_out, int out_size)
{
    const float* x   = (const float*)d_in[0];
    const int*   eiw = (const int*)d_in[1];
    const float* W1  = (const float*)d_in[2];
    const float* b1  = (const float*)d_in[3];
    const float* W2  = (const float*)d_in[4];
    const float* b2  = (const float*)d_in[5];
    float*       out = (float*)d_out;

    const int n = in_sizes[0] / D0;
    int E = in_sizes[1] / 2;
    if (E > EMAX) E = EMAX;

    float *dinv, *h, *agg;
    int *srcp, *dstp, *rankp, *sorted, *cnt, *rowptr;
    cudaGetSymbolAddress((void**)&dinv,   g_dinv);
    cudaGetSymbolAddress((void**)&h,      g_h);
    cudaGetSymbolAddress((void**)&agg,    g_agg);
    cudaGetSymbolAddress((void**)&srcp,   g_src);
    cudaGetSymbolAddress((void**)&dstp,   g_dst);
    cudaGetSymbolAddress((void**)&rankp,  g_rank);
    cudaGetSymbolAddress((void**)&sorted, g_sorted);
    cudaGetSymbolAddress((void**)&cnt,    g_cnt);
    cudaGetSymbolAddress((void**)&rowptr, g_rowptr);

    constexpr int SMEM1 = 1024 + 2 * 128 * 256 + 2 * 128 * 256;
    constexpr int SMEM2 = 1024 + 2 * 128 * 256 + 2 * 64 * 256;
    cudaFuncSetAttribute(tc_gemm<128>, cudaFuncAttributeMaxDynamicSharedMemorySize, SMEM1);
    cudaFuncSetAttribute(tc_gemm<64>,  cudaFuncAttributeMaxDynamicSharedMemorySize, SMEM2);

    // --- CSR build (scan-free) ---
    probe_kernel<<<1, 32>>>(eiw, in_sizes[1]);
    cudaMemsetAsync(cnt, 0, (size_t)n * sizeof(int));
    decode_hist_kernel<<<cdiv(E, 256), 256>>>(eiw, cnt, E, n);
    assign_kernel<<<cdiv(n, 256), 256>>>(cnt, rowptr, dinv, n);
    scatter_sort_kernel<<<cdiv(E, 256), 256>>>(srcp, dstp, rankp, rowptr, sorted, E);

    // --- layer 1 ---
    tc_gemm<D1><<<cdiv(n, 128), 128, SMEM1>>>(x, W1, h, dinv, n);
    aggregate_kernel<D1, true><<<cdiv(n, 8), 256>>>(rowptr, cnt, sorted, h, agg, dinv, b1, n);

    // --- layer 2 ---
    tc_gemm<D2><<<cdiv(n, 128), 128, SMEM2>>>(agg, W2, h, dinv, n);
    aggregate_kernel<D2, false><<<cdiv(n, 8), 256>>>(rowptr, cnt, sorted, h, out, dinv, b2, n);
}

// round 15
// speedup vs baseline: 2.1462x; 1.1814x over previous
#include <cuda_runtime.h>
#include <cuda_bf16.h>
#include <cuda_fp16.h>
#include <cstdint>

// ---------------------------------------------------------------------------
// GCNEncoder: out = GCNConv2( relu( GCNConv1(x) ) )
// Prescale: h_s = (x@W)*dinv (stored fp16) ; agg[d] = sum_in h_s[src] + h_s[d];
// res = dinv[d]*agg + b.  CSR: decode+hist+rank -> order-free assign -> bucket
// scatter.  Aggregate: warp-per-node gather (fp16 loads, fp32 accum).
// GEMMs: tcgen05 bf16 hi/lo split, 256-thread CTAs / FFMA fallback.
// ---------------------------------------------------------------------------

#define NMAX 100000
#define EMAX 1600000
#define D0 128
#define D1 128
#define D2 64

#if defined(__CUDA_ARCH_FEAT_SM103_ALL) || defined(__CUDA_ARCH_FEAT_SM100_ALL) || \
    (defined(__CUDA_ARCH_SPECIFIC__) && (__CUDA_ARCH__ >= 1000))
#define HAS_TCGEN05 1
#else
#define HAS_TCGEN05 0
#endif

__device__ float  g_dinv[NMAX];
__device__ __half g_h[(size_t)NMAX * D1];     // fp16 transform output
__device__ float  g_agg[(size_t)NMAX * D1];   // layer-1 result (fp32)
__device__ int    g_src[EMAX];
__device__ int    g_dst[EMAX];
__device__ int    g_rank[EMAX];
__device__ int    g_sorted[EMAX];
__device__ int    g_cnt[NMAX];
__device__ int    g_rowptr[NMAX];
__device__ int    g_cursor;
__device__ int    g_idx64;

// ---------------------------------------------------------------------------
// PTX helpers
// ---------------------------------------------------------------------------
__device__ __forceinline__ uint32_t smem_u32(const void* p) {
    uint32_t a;
    asm("{ .reg .u64 t; cvta.to.shared.u64 t, %1; cvt.u32.u64 %0, t; }"
        : "=r"(a) : "l"(p));
    return a;
}

#if HAS_TCGEN05
__device__ __forceinline__ uint32_t elect1() {
    uint32_t p;
    asm volatile("{ .reg .pred p; elect.sync _|p, 0xFFFFFFFF; selp.b32 %0,1,0,p; }"
                 : "=r"(p));
    return p;
}

#define TC_ALLOC(smem_addr, ncols) \
    asm volatile("tcgen05.alloc.cta_group::1.sync.aligned.shared::cta.b32 [%0], %1;" \
                 :: "r"(smem_addr), "r"(ncols) : "memory")
#define TC_DEALLOC(tmem, ncols) \
    asm volatile("tcgen05.dealloc.cta_group::1.sync.aligned.b32 %0, %1;" \
                 :: "r"(tmem), "r"(ncols))
#define TC_COMMIT(mbar) \
    asm volatile("tcgen05.commit.cta_group::1.mbarrier::arrive::one.shared::cluster.b64 [%0];" \
                 :: "r"(mbar) : "memory")
#define TC_WAIT_LD() asm volatile("tcgen05.wait::ld.sync.aligned;" ::: "memory")
#define TC_FENCE_AFTER() asm volatile("tcgen05.fence::after_thread_sync;" ::: "memory")
#define MBAR_INIT(mbar, cnt) \
    asm volatile("mbarrier.init.shared.b64 [%0], %1;" :: "r"(mbar), "r"(cnt) : "memory")

#define MBAR_WAIT(mbar, ph) do {                                              \
    uint32_t _done;                                                           \
    asm volatile("{\n\t.reg .pred p;\n\t"                                     \
        "mbarrier.try_wait.parity.acquire.cta.shared::cta.b64 p, [%1], %2;\n\t" \
        "selp.b32 %0,1,0,p;\n\t}"                                             \
        : "=r"(_done) : "r"(mbar), "r"(ph) : "memory");                       \
    if (!_done) {                                                             \
        asm volatile("{\n\t.reg .pred P1;\n\t"                                \
            "W1_%=:\n\t"                                                      \
            "mbarrier.try_wait.parity.acquire.cta.shared::cta.b64 P1, [%0], %1, 0x989680;\n\t" \
            "@P1 bra.uni W2_%=;\n\tbra.uni W1_%=;\n\tW2_%=:\n\t}"             \
            :: "r"(mbar), "r"(ph) : "memory");                                \
    }                                                                         \
} while (0)

#define TC_LD_X32(r, tmem)                                                    \
    asm volatile("tcgen05.ld.sync.aligned.32x32b.x32.b32 "                    \
        "{%0, %1, %2, %3, %4, %5, %6, %7, "                                   \
        " %8, %9, %10, %11, %12, %13, %14, %15, "                             \
        " %16, %17, %18, %19, %20, %21, %22, %23, "                           \
        " %24, %25, %26, %27, %28, %29, %30, %31}, [%32];"                    \
        : "=r"((r)[0]),  "=r"((r)[1]),  "=r"((r)[2]),  "=r"((r)[3]),          \
          "=r"((r)[4]),  "=r"((r)[5]),  "=r"((r)[6]),  "=r"((r)[7]),          \
          "=r"((r)[8]),  "=r"((r)[9]),  "=r"((r)[10]), "=r"((r)[11]),         \
          "=r"((r)[12]), "=r"((r)[13]), "=r"((r)[14]), "=r"((r)[15]),         \
          "=r"((r)[16]), "=r"((r)[17]), "=r"((r)[18]), "=r"((r)[19]),         \
          "=r"((r)[20]), "=r"((r)[21]), "=r"((r)[22]), "=r"((r)[23]),         \
          "=r"((r)[24]), "=r"((r)[25]), "=r"((r)[26]), "=r"((r)[27]),         \
          "=r"((r)[28]), "=r"((r)[29]), "=r"((r)[30]), "=r"((r)[31])          \
        : "r"(tmem))

__device__ __forceinline__ void mma_ss_f16(uint32_t d, uint64_t a, uint64_t b,
                                           uint32_t idesc, bool acc) {
    uint32_t e = acc ? 1u : 0u;
    asm volatile(
        "{\n\t.reg .pred p;\n\tsetp.ne.u32 p, %4, 0;\n\t"
        "tcgen05.mma.cta_group::1.kind::f16 [%0], %1, %2, %3, {%5,%5,%5,%5}, p;\n\t}"
        :: "r"(d), "l"(a), "l"(b), "r"(idesc), "r"(e), "r"(0u)
        : "memory");
}
#endif  // HAS_TCGEN05

// SW128 blocked-atom offset: atom = 8 rows x 64 bf16 (1024B), col-major atoms.
template <int ROWS>
__device__ __forceinline__ uint32_t sw_off(int r, int c) {
    uint32_t atom = (uint32_t)(r >> 3) + (uint32_t)(c >> 6) * (ROWS >> 3);
    uint32_t off = atom * 1024 + (r & 7) * 128 + (c & 63) * 2;
    return off ^ ((off >> 3) & 0x70);
}

__device__ __forceinline__ void split4(float4 v, unsigned long long& hi,
                                       unsigned long long& lo) {
    __nv_bfloat16 h0 = __float2bfloat16(v.x), h1 = __float2bfloat16(v.y);
    __nv_bfloat16 h2 = __float2bfloat16(v.z), h3 = __float2bfloat16(v.w);
    __nv_bfloat16 l0 = __float2bfloat16(v.x - __bfloat162float(h0));
    __nv_bfloat16 l1 = __float2bfloat16(v.y - __bfloat162float(h1));
    __nv_bfloat16 l2 = __float2bfloat16(v.z - __bfloat162float(h2));
    __nv_bfloat16 l3 = __float2bfloat16(v.w - __bfloat162float(h3));
    hi = (unsigned long long)__bfloat16_as_ushort(h0)
       | ((unsigned long long)__bfloat16_as_ushort(h1) << 16)
       | ((unsigned long long)__bfloat16_as_ushort(h2) << 32)
       | ((unsigned long long)__bfloat16_as_ushort(h3) << 48);
    lo = (unsigned long long)__bfloat16_as_ushort(l0)
       | ((unsigned long long)__bfloat16_as_ushort(l1) << 16)
       | ((unsigned long long)__bfloat16_as_ushort(l2) << 32)
       | ((unsigned long long)__bfloat16_as_ushort(l3) << 48);
}

// ---------------------------------------------------------------------------
// GEMM: C[r,:] = (half) dinv[r] * (A[r,:] @ W)   (A fp32 [n,128], C fp16)
// 256 threads: 2 threads per row in convert phase; 8 warps in epilogue.
// ---------------------------------------------------------------------------
template <int OUT>
__global__ void __launch_bounds__(256) tc_gemm(
    const float* __restrict__ A, const float* __restrict__ W,
    __half* __restrict__ C, const float* __restrict__ dinv, int n)
{
    extern __shared__ char smem[];
    constexpr int K = 128;
    const int tid = threadIdx.x;
    const int row0 = blockIdx.x * 128;

#if HAS_TCGEN05
    constexpr uint32_t A_HI = 1024;
    constexpr uint32_t A_LO = A_HI + 128 * 256;
    constexpr uint32_t B_HI = A_LO + 128 * 256;
    constexpr uint32_t B_LO = B_HI + OUT * 256;

    const uint32_t sb = smem_u32(smem);
    const int wid = tid >> 5, lane = tid & 31;

    if (wid == 0) TC_ALLOC(sb + 0, 128);
    __syncthreads();
    uint32_t tmem;
    asm volatile("ld.shared.b32 %0, [%1];" : "=r"(tmem) : "r"(sb + 0));

    // --- A tile: 2 threads per row, 64 cols each ---
    {
        int r = row0 + (tid >> 1);
        int c0 = (tid & 1) * 64;
        if (r < n) {
            const float4* src = (const float4*)&A[(size_t)r * K + c0];
#pragma unroll
            for (int c = 0; c < 64; c += 4) {
                unsigned long long hi, lo;
                split4(src[c >> 2], hi, lo);
                uint32_t o = sw_off<128>(tid >> 1, c0 + c);
                *(unsigned long long*)(smem + A_HI + o) = hi;
                *(unsigned long long*)(smem + A_LO + o) = lo;
            }
        } else {
#pragma unroll
            for (int c = 0; c < 64; c += 4) {
                uint32_t o = sw_off<128>(tid >> 1, c0 + c);
                *(unsigned long long*)(smem + A_HI + o) = 0ull;
                *(unsigned long long*)(smem + A_LO + o) = 0ull;
            }
        }
    }

    // --- B tile: B[nrow][k] = W[k][nrow] (transpose load, hi/lo split) ---
    {
        int br, k0, kcnt;
        if (OUT == 128) { br = tid >> 1; k0 = (tid & 1) * 64; kcnt = 64; }
        else { br = tid & 63; k0 = (tid >> 6) * 32; kcnt = 32; }
#pragma unroll 4
        for (int k = k0; k < k0 + kcnt; k += 4) {
            float4 v = make_float4(W[(size_t)(k + 0) * OUT + br],
                                   W[(size_t)(k + 1) * OUT + br],
                                   W[(size_t)(k + 2) * OUT + br],
                                   W[(size_t)(k + 3) * OUT + br]);
            unsigned long long hi, lo;
            split4(v, hi, lo);
            uint32_t o = sw_off<OUT>(br, k);
            *(unsigned long long*)(smem + B_HI + o) = hi;
            *(unsigned long long*)(smem + B_LO + o) = lo;
        }
    }
    asm volatile("fence.proxy.async.shared::cta;" ::: "memory");
    __syncthreads();

    if (tid == 0) MBAR_INIT(sb + 8, 1);
    __syncthreads();

    if (wid == 0) {
        if (elect1()) {
            const uint64_t DB = (2ull << 61) | (1ull << 46) | (64ull << 32) | (1ull << 16);
            uint64_t dAhi = DB | (((sb + A_HI) >> 4) & 0x3FFF);
            uint64_t dAlo = DB | (((sb + A_LO) >> 4) & 0x3FFF);
            uint64_t dBhi = DB | (((sb + B_HI) >> 4) & 0x3FFF);
            uint64_t dBlo = DB | (((sb + B_LO) >> 4) & 0x3FFF);
            constexpr uint32_t idesc =
                (1u << 4) | (1u << 7) | (1u << 10) | ((OUT / 8) << 17) | (8u << 24);
            bool first = true;
#pragma unroll
            for (int s = 0; s < 8; s++) {
                uint64_t ao = (s < 4) ? (uint64_t)(s * 2) : (uint64_t)(1024 + (s - 4) * 2);
                uint64_t bo = (s < 4) ? (uint64_t)(s * 2) : (uint64_t)(OUT * 8 + (s - 4) * 2);
                mma_ss_f16(tmem, dAhi + ao, dBhi + bo, idesc, !first);
                first = false;
                mma_ss_f16(tmem, dAhi + ao, dBlo + bo, idesc, true);
                mma_ss_f16(tmem, dAlo + ao, dBhi + bo, idesc, true);
            }
            TC_COMMIT(sb + 8);
        }
    }

    MBAR_WAIT(sb + 8, 0);
    TC_FENCE_AFTER();

    // --- epilogue: 8 warps; warp w: rows (w%4)*32+lane, column half w/4 ---
    {
        constexpr int CH = OUT / 2;          // cols per warp: 64 or 32
        int sp = wid & 3, hf = wid >> 2;
        int r = row0 + sp * 32 + lane;
        float sc = (r < n) ? dinv[r] : 0.f;
#pragma unroll
        for (int ch = 0; ch < CH; ch += 32) {
            uint32_t rg[32];
            TC_LD_X32(rg, tmem + hf * CH + ch);
            TC_WAIT_LD();
            if (r < n) {
#pragma unroll
                for (int q = 0; q < 4; q++) {
                    uint32_t h2[4];
#pragma unroll
                    for (int j = 0; j < 4; j++) {
                        __half2 hh = __floats2half2_rn(
                            __uint_as_float(rg[q * 8 + j * 2 + 0]) * sc,
                            __uint_as_float(rg[q * 8 + j * 2 + 1]) * sc);
                        h2[j] = *(uint32_t*)&hh;
                    }
                    *(uint4*)&C[(size_t)r * OUT + hf * CH + ch + q * 8] =
                        make_uint4(h2[0], h2[1], h2[2], h2[3]);
                }
            }
        }
    }

    __syncthreads();
    if (wid == 0) {
        if (elect1())
            asm volatile("mbarrier.inval.shared.b64 [%0];" :: "r"(sb + 8) : "memory");
        TC_DEALLOC(tmem, 128);
    }

#else  // FFMA fallback (virtual-arch build), 256 threads, 128 rows/CTA
    constexpr int NTX = OUT / 8;          // 16 or 8
    constexpr int NTY = 256 / NTX;        // 16 or 32
    constexpr int RPT = 128 / NTY;        // 8 or 4
    float* As = (float*)smem;             // [8][128]
    float* Bs = (float*)(smem + 8 * 128 * 4);  // [8][OUT]

    const int tx = tid % NTX;
    const int ty = tid / NTX;

    float acc[RPT][8];
#pragma unroll
    for (int i = 0; i < RPT; i++)
#pragma unroll
        for (int j = 0; j < 8; j++) acc[i][j] = 0.f;

    for (int k0 = 0; k0 < K; k0 += 8) {
        int ar = tid >> 1, ac = (tid & 1) << 2;
        float4 av = make_float4(0.f, 0.f, 0.f, 0.f);
        if (row0 + ar < n)
            av = *(const float4*)&A[(size_t)(row0 + ar) * K + k0 + ac];
        As[(ac + 0) * 128 + ar] = av.x;
        As[(ac + 1) * 128 + ar] = av.y;
        As[(ac + 2) * 128 + ar] = av.z;
        As[(ac + 3) * 128 + ar] = av.w;
#pragma unroll
        for (int i = tid; i < 8 * OUT; i += 256)
            Bs[i] = W[(size_t)(k0 + i / OUT) * OUT + (i % OUT)];
        __syncthreads();
#pragma unroll
        for (int k = 0; k < 8; k++) {
            float a[RPT], b[8];
#pragma unroll
            for (int i = 0; i < RPT; i++) a[i] = As[k * 128 + ty * RPT + i];
            *(float4*)&b[0] = *(float4*)&Bs[k * OUT + tx * 8];
            *(float4*)&b[4] = *(float4*)&Bs[k * OUT + tx * 8 + 4];
#pragma unroll
            for (int i = 0; i < RPT; i++)
#pragma unroll
                for (int j = 0; j < 8; j++) acc[i][j] += a[i] * b[j];
        }
        __syncthreads();
    }

#pragma unroll
    for (int i = 0; i < RPT; i++) {
        int r = row0 + ty * RPT + i;
        if (r < n) {
            float sc = dinv[r];
            uint32_t h2[4];
#pragma unroll
            for (int j = 0; j < 4; j++) {
                __half2 hh = __floats2half2_rn(acc[i][j * 2] * sc,
                                               acc[i][j * 2 + 1] * sc);
                h2[j] = *(uint32_t*)&hh;
            }
            *(uint4*)&C[(size_t)r * OUT + tx * 8] = make_uint4(h2[0], h2[1], h2[2], h2[3]);
        }
    }
#endif
}

// ---------------------------------------------------------------------------
// CSR build
// ---------------------------------------------------------------------------
__global__ void probe_kernel(const int* __restrict__ w, int nwords) {
    if (threadIdx.x == 0 && blockIdx.x == 0) {
        int limit = nwords < 2048 ? nwords : 2048;
        int acc = 0;
        for (int i = 1; i < limit; i += 2) acc |= w[i];
        g_idx64 = (acc == 0) ? 1 : 0;
        g_cursor = 0;
    }
}

__global__ void decode_hist_kernel(const int* __restrict__ w, int* cnt,
                                   int E, int n) {
    int e = blockIdx.x * blockDim.x + threadIdx.x;
    if (e >= E) return;
    int s, d;
    if (g_idx64) {
        s = w[2 * (size_t)e];
        d = w[2 * ((size_t)E + e)];
    } else {
        s = w[e];
        d = w[(size_t)E + e];
    }
    if ((unsigned)s >= (unsigned)n) s = 0;
    if ((unsigned)d >= (unsigned)n) d = 0;
    g_src[e] = s;
    g_dst[e] = d;
    g_rank[e] = atomicAdd(&cnt[d], 1);
}

// Order-free segment assignment + dinv.
__global__ void assign_kernel(const int* __restrict__ cnt, int* rowptr,
                              float* dinv, int n) {
    int i = blockIdx.x * blockDim.x + threadIdx.x;
    if (i >= n) return;
    int c = cnt[i];
    rowptr[i] = (c > 0) ? atomicAdd(&g_cursor, c) : 0;
    dinv[i] = rsqrtf(1.0f + (float)c);  // +1 self-loop
}

__global__ void scatter_sort_kernel(const int* __restrict__ src,
                                    const int* __restrict__ dst,
                                    const int* __restrict__ rank,
                                    const int* __restrict__ rowptr,
                                    int* sorted, int E) {
    int e = blockIdx.x * blockDim.x + threadIdx.x;
    if (e >= E) return;
    sorted[rowptr[dst[e]] + rank[e]] = src[e];
}

// ---------------------------------------------------------------------------
// Fused aggregate: res[d] = f( dinv[d] * (sum_in h[src] + h[d]) + bias )
// h is fp16 (prescaled); accumulate fp32.  One warp per dst node.
// ---------------------------------------------------------------------------
__device__ __forceinline__ void ld4h(const __half* p, float* f) {
    uint2 u = *(const uint2*)p;
    float2 a = __half22float2(*(__half2*)&u.x);
    float2 b = __half22float2(*(__half2*)&u.y);
    f[0] = a.x; f[1] = a.y; f[2] = b.x; f[3] = b.y;
}
__device__ __forceinline__ void ld2h(const __half* p, float* f) {
    uint32_t u = *(const uint32_t*)p;
    float2 a = __half22float2(*(__half2*)&u);
    f[0] = a.x; f[1] = a.y;
}

template <int DIM, bool RELU>
__global__ void __launch_bounds__(256) aggregate_kernel(
    const int* __restrict__ rowptr, const int* __restrict__ cnt,
    const int* __restrict__ sorted,
    const __half* __restrict__ h, float* __restrict__ res,
    const float* __restrict__ dinv, const float* __restrict__ bias, int n)
{
    constexpr int VPL = DIM / 32;  // halves per lane: 4 (D=128) or 2 (D=64)
    int node = (int)((blockIdx.x * (long long)blockDim.x + threadIdx.x) >> 5);
    int lane = threadIdx.x & 31;
    if (node >= n) return;

    const int beg = rowptr[node];
    const int end = beg + cnt[node];
    const int col = lane * VPL;

    float acc[VPL];
    if (VPL == 4) ld4h(&h[(size_t)node * DIM + col], acc);
    else          ld2h(&h[(size_t)node * DIM + col], acc);

    int e = beg;
    for (; e + 4 <= end; e += 4) {
        int s0 = sorted[e + 0], s1 = sorted[e + 1];
        int s2 = sorted[e + 2], s3 = sorted[e + 3];
        float v0[VPL], v1[VPL], v2[VPL], v3[VPL];
        if (VPL == 4) {
            ld4h(&h[(size_t)s0 * DIM + col], v0);
            ld4h(&h[(size_t)s1 * DIM + col], v1);
            ld4h(&h[(size_t)s2 * DIM + col], v2);
            ld4h(&h[(size_t)s3 * DIM + col], v3);
        } else {
            ld2h(&h[(size_t)s0 * DIM + col], v0);
            ld2h(&h[(size_t)s1 * DIM + col], v1);
            ld2h(&h[(size_t)s2 * DIM + col], v2);
            ld2h(&h[(size_t)s3 * DIM + col], v3);
        }
#pragma unroll
        for (int j = 0; j < VPL; j++)
            acc[j] += (v0[j] + v1[j]) + (v2[j] + v3[j]);
    }
    for (; e < end; e++) {
        int s = sorted[e];
        float v[VPL];
        if (VPL == 4) ld4h(&h[(size_t)s * DIM + col], v);
        else          ld2h(&h[(size_t)s * DIM + col], v);
#pragma unroll
        for (int j = 0; j < VPL; j++) acc[j] += v[j];
    }

    float di = dinv[node];
    if (VPL == 4) {
        float4 b = *(const float4*)&bias[col];
        float4 r;
        r.x = di * acc[0] + b.x;
        r.y = di * acc[1] + b.y;
        r.z = di * acc[2] + b.z;
        r.w = di * acc[3] + b.w;
        if (RELU) {
            r.x = fmaxf(r.x, 0.f); r.y = fmaxf(r.y, 0.f);
            r.z = fmaxf(r.z, 0.f); r.w = fmaxf(r.w, 0.f);
        }
        *(float4*)&res[(size_t)node * DIM + col] = r;
    } else {
        float2 b = *(const float2*)&bias[col];
        float2 r;
        r.x = di * acc[0] + b.x;
        r.y = di * acc[1] + b.y;
        if (RELU) { r.x = fmaxf(r.x, 0.f); r.y = fmaxf(r.y, 0.f); }
        *(float2*)&res[(size_t)node * DIM + col] = r;
    }
}

// ---------------------------------------------------------------------------
// launch
// ---------------------------------------------------------------------------
static inline int cdiv(long long a, long long b) { return (int)((a + b - 1) / b); }

extern "C" void kernel_launch(void* const* d_in, const int* in_sizes, int n_in,
                              void* d_out, int out_size)
{
    const float* x   = (const float*)d_in[0];
    const int*   eiw = (const int*)d_in[1];
    const float* W1  = (const float*)d_in[2];
    const float* b1  = (const float*)d_in[3];
    const float* W2  = (const float*)d_in[4];
    const float* b2  = (const float*)d_in[5];
    float*       out = (float*)d_out;

    const int n = in_sizes[0] / D0;
    int E = in_sizes[1] / 2;
    if (E > EMAX) E = EMAX;

    float *dinv, *agg;
    __half* h;
    int *srcp, *dstp, *rankp, *sorted, *cnt, *rowptr;
    cudaGetSymbolAddress((void**)&dinv,   g_dinv);
    cudaGetSymbolAddress((void**)&h,      g_h);
    cudaGetSymbolAddress((void**)&agg,    g_agg);
    cudaGetSymbolAddress((void**)&srcp,   g_src);
    cudaGetSymbolAddress((void**)&dstp,   g_dst);
    cudaGetSymbolAddress((void**)&rankp,  g_rank);
    cudaGetSymbolAddress((void**)&sorted, g_sorted);
    cudaGetSymbolAddress((void**)&cnt,    g_cnt);
    cudaGetSymbolAddress((void**)&rowptr, g_rowptr);

    constexpr int SMEM1 = 1024 + 2 * 128 * 256 + 2 * 128 * 256;
    constexpr int SMEM2 = 1024 + 2 * 128 * 256 + 2 * 64 * 256;
    cudaFuncSetAttribute(tc_gemm<128>, cudaFuncAttributeMaxDynamicSharedMemorySize, SMEM1);
    cudaFuncSetAttribute(tc_gemm<64>,  cudaFuncAttributeMaxDynamicSharedMemorySize, SMEM2);

    // --- CSR build (scan-free) ---
    probe_kernel<<<1, 32>>>(eiw, in_sizes[1]);
    cudaMemsetAsync(cnt, 0, (size_t)n * sizeof(int));
    decode_hist_kernel<<<cdiv(E, 256), 256>>>(eiw, cnt, E, n);
    assign_kernel<<<cdiv(n, 256), 256>>>(cnt, rowptr, dinv, n);
    scatter_sort_kernel<<<cdiv(E, 256), 256>>>(srcp, dstp, rankp, rowptr, sorted, E);

    // --- layer 1 ---
    tc_gemm<D1><<<cdiv(n, 128), 256, SMEM1>>>(x, W1, h, dinv, n);
    aggregate_kernel<D1, true><<<cdiv(n, 8), 256>>>(rowptr, cnt, sorted, h, agg, dinv, b1, n);

    // --- layer 2 ---
    tc_gemm<D2><<<cdiv(n, 128), 256, SMEM2>>>(agg, W2, h, dinv, n);
    aggregate_kernel<D2, false><<<cdiv(n, 8), 256>>>(rowptr, cnt, sorted, h, out, dinv, b2, n);
}

// round 16
// speedup vs baseline: 2.4653x; 1.1486x over previous
#include <cuda_runtime.h>
#include <cuda_bf16.h>
#include <cuda_fp16.h>
#include <cstdint>

// ---------------------------------------------------------------------------
// GCNEncoder: out = GCNConv2( relu( GCNConv1(x) ) )
// Prescale: h_s = (x@W)*dinv (fp16) ; agg[d] = sum_in h_s[src] + h_s[d] (fp16);
// res = dinv[d]*agg + b.  CSR: init(probe+zero) -> decode+hist+rank ->
// order-free assign -> bucket scatter.  Aggregate: warp-per-node fp16 gather.
// GEMMs: tcgen05 bf16 hi/lo split (fp32 or fp16 input) / FFMA fallback.
// ---------------------------------------------------------------------------

#define NMAX 100000
#define EMAX 1600000
#define D0 128
#define D1 128
#define D2 64

#if defined(__CUDA_ARCH_FEAT_SM103_ALL) || defined(__CUDA_ARCH_FEAT_SM100_ALL) || \
    (defined(__CUDA_ARCH_SPECIFIC__) && (__CUDA_ARCH__ >= 1000))
#define HAS_TCGEN05 1
#else
#define HAS_TCGEN05 0
#endif

__device__ float  g_dinv[NMAX];
__device__ __half g_h[(size_t)NMAX * D1];     // fp16 transform output
__device__ __half g_agg[(size_t)NMAX * D1];   // fp16 layer-1 result
__device__ int    g_src[EMAX];
__device__ int    g_dst[EMAX];
__device__ int    g_rank[EMAX];
__device__ int    g_sorted[EMAX];
__device__ int    g_cnt[NMAX];
__device__ int    g_rowptr[NMAX];
__device__ int    g_cursor;
__device__ int    g_idx64;

// ---------------------------------------------------------------------------
// PTX helpers
// ---------------------------------------------------------------------------
__device__ __forceinline__ uint32_t smem_u32(const void* p) {
    uint32_t a;
    asm("{ .reg .u64 t; cvta.to.shared.u64 t, %1; cvt.u32.u64 %0, t; }"
        : "=r"(a) : "l"(p));
    return a;
}

#if HAS_TCGEN05
__device__ __forceinline__ uint32_t elect1() {
    uint32_t p;
    asm volatile("{ .reg .pred p; elect.sync _|p, 0xFFFFFFFF; selp.b32 %0,1,0,p; }"
                 : "=r"(p));
    return p;
}

#define TC_ALLOC(smem_addr, ncols) \
    asm volatile("tcgen05.alloc.cta_group::1.sync.aligned.shared::cta.b32 [%0], %1;" \
                 :: "r"(smem_addr), "r"(ncols) : "memory")
#define TC_DEALLOC(tmem, ncols) \
    asm volatile("tcgen05.dealloc.cta_group::1.sync.aligned.b32 %0, %1;" \
                 :: "r"(tmem), "r"(ncols))
#define TC_COMMIT(mbar) \
    asm volatile("tcgen05.commit.cta_group::1.mbarrier::arrive::one.shared::cluster.b64 [%0];" \
                 :: "r"(mbar) : "memory")
#define TC_WAIT_LD() asm volatile("tcgen05.wait::ld.sync.aligned;" ::: "memory")
#define TC_FENCE_AFTER() asm volatile("tcgen05.fence::after_thread_sync;" ::: "memory")
#define MBAR_INIT(mbar, cnt) \
    asm volatile("mbarrier.init.shared.b64 [%0], %1;" :: "r"(mbar), "r"(cnt) : "memory")

#define MBAR_WAIT(mbar, ph) do {                                              \
    uint32_t _done;                                                           \
    asm volatile("{\n\t.reg .pred p;\n\t"                                     \
        "mbarrier.try_wait.parity.acquire.cta.shared::cta.b64 p, [%1], %2;\n\t" \
        "selp.b32 %0,1,0,p;\n\t}"                                             \
        : "=r"(_done) : "r"(mbar), "r"(ph) : "memory");                       \
    if (!_done) {                                                             \
        asm volatile("{\n\t.reg .pred P1;\n\t"                                \
            "W1_%=:\n\t"                                                      \
            "mbarrier.try_wait.parity.acquire.cta.shared::cta.b64 P1, [%0], %1, 0x989680;\n\t" \
            "@P1 bra.uni W2_%=;\n\tbra.uni W1_%=;\n\tW2_%=:\n\t}"             \
            :: "r"(mbar), "r"(ph) : "memory");                                \
    }                                                                         \
} while (0)

#define TC_LD_X32(r, tmem)                                                    \
    asm volatile("tcgen05.ld.sync.aligned.32x32b.x32.b32 "                    \
        "{%0, %1, %2, %3, %4, %5, %6, %7, "                                   \
        " %8, %9, %10, %11, %12, %13, %14, %15, "                             \
        " %16, %17, %18, %19, %20, %21, %22, %23, "                           \
        " %24, %25, %26, %27, %28, %29, %30, %31}, [%32];"                    \
        : "=r"((r)[0]),  "=r"((r)[1]),  "=r"((r)[2]),  "=r"((r)[3]),          \
          "=r"((r)[4]),  "=r"((r)[5]),  "=r"((r)[6]),  "=r"((r)[7]),          \
          "=r"((r)[8]),  "=r"((r)[9]),  "=r"((r)[10]), "=r"((r)[11]),         \
          "=r"((r)[12]), "=r"((r)[13]), "=r"((r)[14]), "=r"((r)[15]),         \
          "=r"((r)[16]), "=r"((r)[17]), "=r"((r)[18]), "=r"((r)[19]),         \
          "=r"((r)[20]), "=r"((r)[21]), "=r"((r)[22]), "=r"((r)[23]),         \
          "=r"((r)[24]), "=r"((r)[25]), "=r"((r)[26]), "=r"((r)[27]),         \
          "=r"((r)[28]), "=r"((r)[29]), "=r"((r)[30]), "=r"((r)[31])          \
        : "r"(tmem))

__device__ __forceinline__ void mma_ss_f16(uint32_t d, uint64_t a, uint64_t b,
                                           uint32_t idesc, bool acc) {
    uint32_t e = acc ? 1u : 0u;
    asm volatile(
        "{\n\t.reg .pred p;\n\tsetp.ne.u32 p, %4, 0;\n\t"
        "tcgen05.mma.cta_group::1.kind::f16 [%0], %1, %2, %3, {%5,%5,%5,%5}, p;\n\t}"
        :: "r"(d), "l"(a), "l"(b), "r"(idesc), "r"(e), "r"(0u)
        : "memory");
}
#endif  // HAS_TCGEN05

// SW128 blocked-atom offset: atom = 8 rows x 64 bf16 (1024B), col-major atoms.
template <int ROWS>
__device__ __forceinline__ uint32_t sw_off(int r, int c) {
    uint32_t atom = (uint32_t)(r >> 3) + (uint32_t)(c >> 6) * (ROWS >> 3);
    uint32_t off = atom * 1024 + (r & 7) * 128 + (c & 63) * 2;
    return off ^ ((off >> 3) & 0x70);
}

__device__ __forceinline__ void split4(float4 v, unsigned long long& hi,
                                       unsigned long long& lo) {
    __nv_bfloat16 h0 = __float2bfloat16(v.x), h1 = __float2bfloat16(v.y);
    __nv_bfloat16 h2 = __float2bfloat16(v.z), h3 = __float2bfloat16(v.w);
    __nv_bfloat16 l0 = __float2bfloat16(v.x - __bfloat162float(h0));
    __nv_bfloat16 l1 = __float2bfloat16(v.y - __bfloat162float(h1));
    __nv_bfloat16 l2 = __float2bfloat16(v.z - __bfloat162float(h2));
    __nv_bfloat16 l3 = __float2bfloat16(v.w - __bfloat162float(h3));
    hi = (unsigned long long)__bfloat16_as_ushort(h0)
       | ((unsigned long long)__bfloat16_as_ushort(h1) << 16)
       | ((unsigned long long)__bfloat16_as_ushort(h2) << 32)
       | ((unsigned long long)__bfloat16_as_ushort(h3) << 48);
    lo = (unsigned long long)__bfloat16_as_ushort(l0)
       | ((unsigned long long)__bfloat16_as_ushort(l1) << 16)
       | ((unsigned long long)__bfloat16_as_ushort(l2) << 32)
       | ((unsigned long long)__bfloat16_as_ushort(l3) << 48);
}

// input loaders: fp32 direct, fp16 via convert
__device__ __forceinline__ float4 loadA4(const float* p) {
    return *(const float4*)p;
}
__device__ __forceinline__ float4 loadA4(const __half* p) {
    uint2 u = *(const uint2*)p;
    float2 a = __half22float2(*(__half2*)&u.x);
    float2 b = __half22float2(*(__half2*)&u.y);
    return make_float4(a.x, a.y, b.x, b.y);
}

// ---------------------------------------------------------------------------
// GEMM: C[r,:] = (half) dinv[r] * (A[r,:] @ W)   (A fp32 or fp16, C fp16)
// 256 threads: 2 threads per row in convert phase; 8 warps in epilogue.
// ---------------------------------------------------------------------------
template <int OUT, typename AT>
__global__ void __launch_bounds__(256) tc_gemm(
    const AT* __restrict__ A, const float* __restrict__ W,
    __half* __restrict__ C, const float* __restrict__ dinv, int n)
{
    extern __shared__ char smem[];
    constexpr int K = 128;
    const int tid = threadIdx.x;
    const int row0 = blockIdx.x * 128;

#if HAS_TCGEN05
    constexpr uint32_t A_HI = 1024;
    constexpr uint32_t A_LO = A_HI + 128 * 256;
    constexpr uint32_t B_HI = A_LO + 128 * 256;
    constexpr uint32_t B_LO = B_HI + OUT * 256;

    const uint32_t sb = smem_u32(smem);
    const int wid = tid >> 5, lane = tid & 31;

    if (wid == 0) TC_ALLOC(sb + 0, 128);
    __syncthreads();
    uint32_t tmem;
    asm volatile("ld.shared.b32 %0, [%1];" : "=r"(tmem) : "r"(sb + 0));

    // --- A tile: 2 threads per row, 64 cols each ---
    {
        int r = row0 + (tid >> 1);
        int c0 = (tid & 1) * 64;
        if (r < n) {
            const AT* src = &A[(size_t)r * K + c0];
#pragma unroll
            for (int c = 0; c < 64; c += 4) {
                unsigned long long hi, lo;
                split4(loadA4(src + c), hi, lo);
                uint32_t o = sw_off<128>(tid >> 1, c0 + c);
                *(unsigned long long*)(smem + A_HI + o) = hi;
                *(unsigned long long*)(smem + A_LO + o) = lo;
            }
        } else {
#pragma unroll
            for (int c = 0; c < 64; c += 4) {
                uint32_t o = sw_off<128>(tid >> 1, c0 + c);
                *(unsigned long long*)(smem + A_HI + o) = 0ull;
                *(unsigned long long*)(smem + A_LO + o) = 0ull;
            }
        }
    }

    // --- B tile: B[nrow][k] = W[k][nrow] (transpose load, hi/lo split) ---
    {
        int br, k0, kcnt;
        if (OUT == 128) { br = tid >> 1; k0 = (tid & 1) * 64; kcnt = 64; }
        else { br = tid & 63; k0 = (tid >> 6) * 32; kcnt = 32; }
#pragma unroll 4
        for (int k = k0; k < k0 + kcnt; k += 4) {
            float4 v = make_float4(W[(size_t)(k + 0) * OUT + br],
                                   W[(size_t)(k + 1) * OUT + br],
                                   W[(size_t)(k + 2) * OUT + br],
                                   W[(size_t)(k + 3) * OUT + br]);
            unsigned long long hi, lo;
            split4(v, hi, lo);
            uint32_t o = sw_off<OUT>(br, k);
            *(unsigned long long*)(smem + B_HI + o) = hi;
            *(unsigned long long*)(smem + B_LO + o) = lo;
        }
    }
    asm volatile("fence.proxy.async.shared::cta;" ::: "memory");
    __syncthreads();

    if (tid == 0) MBAR_INIT(sb + 8, 1);
    __syncthreads();

    if (wid == 0) {
        if (elect1()) {
            const uint64_t DB = (2ull << 61) | (1ull << 46) | (64ull << 32) | (1ull << 16);
            uint64_t dAhi = DB | (((sb + A_HI) >> 4) & 0x3FFF);
            uint64_t dAlo = DB | (((sb + A_LO) >> 4) & 0x3FFF);
            uint64_t dBhi = DB | (((sb + B_HI) >> 4) & 0x3FFF);
            uint64_t dBlo = DB | (((sb + B_LO) >> 4) & 0x3FFF);
            constexpr uint32_t idesc =
                (1u << 4) | (1u << 7) | (1u << 10) | ((OUT / 8) << 17) | (8u << 24);
            bool first = true;
#pragma unroll
            for (int s = 0; s < 8; s++) {
                uint64_t ao = (s < 4) ? (uint64_t)(s * 2) : (uint64_t)(1024 + (s - 4) * 2);
                uint64_t bo = (s < 4) ? (uint64_t)(s * 2) : (uint64_t)(OUT * 8 + (s - 4) * 2);
                mma_ss_f16(tmem, dAhi + ao, dBhi + bo, idesc, !first);
                first = false;
                mma_ss_f16(tmem, dAhi + ao, dBlo + bo, idesc, true);
                mma_ss_f16(tmem, dAlo + ao, dBhi + bo, idesc, true);
            }
            TC_COMMIT(sb + 8);
        }
    }

    MBAR_WAIT(sb + 8, 0);
    TC_FENCE_AFTER();

    // --- epilogue: 8 warps; warp w: rows (w%4)*32+lane, column half w/4 ---
    {
        constexpr int CH = OUT / 2;          // cols per warp: 64 or 32
        int sp = wid & 3, hf = wid >> 2;
        int r = row0 + sp * 32 + lane;
        float sc = (r < n) ? dinv[r] : 0.f;
#pragma unroll
        for (int ch = 0; ch < CH; ch += 32) {
            uint32_t rg[32];
            TC_LD_X32(rg, tmem + hf * CH + ch);
            TC_WAIT_LD();
            if (r < n) {
#pragma unroll
                for (int q = 0; q < 4; q++) {
                    uint32_t h2[4];
#pragma unroll
                    for (int j = 0; j < 4; j++) {
                        __half2 hh = __floats2half2_rn(
                            __uint_as_float(rg[q * 8 + j * 2 + 0]) * sc,
                            __uint_as_float(rg[q * 8 + j * 2 + 1]) * sc);
                        h2[j] = *(uint32_t*)&hh;
                    }
                    *(uint4*)&C[(size_t)r * OUT + hf * CH + ch + q * 8] =
                        make_uint4(h2[0], h2[1], h2[2], h2[3]);
                }
            }
        }
    }

    __syncthreads();
    if (wid == 0) {
        if (elect1())
            asm volatile("mbarrier.inval.shared.b64 [%0];" :: "r"(sb + 8) : "memory");
        TC_DEALLOC(tmem, 128);
    }

#else  // FFMA fallback (virtual-arch build), 256 threads, 128 rows/CTA
    constexpr int NTX = OUT / 8;          // 16 or 8
    constexpr int NTY = 256 / NTX;        // 16 or 32
    constexpr int RPT = 128 / NTY;        // 8 or 4
    float* As = (float*)smem;             // [8][128]
    float* Bs = (float*)(smem + 8 * 128 * 4);  // [8][OUT]

    const int tx = tid % NTX;
    const int ty = tid / NTX;

    float acc[RPT][8];
#pragma unroll
    for (int i = 0; i < RPT; i++)
#pragma unroll
        for (int j = 0; j < 8; j++) acc[i][j] = 0.f;

    for (int k0 = 0; k0 < K; k0 += 8) {
        int ar = tid >> 1, ac = (tid & 1) << 2;
        float4 av = make_float4(0.f, 0.f, 0.f, 0.f);
        if (row0 + ar < n)
            av = loadA4(&A[(size_t)(row0 + ar) * K + k0 + ac]);
        As[(ac + 0) * 128 + ar] = av.x;
        As[(ac + 1) * 128 + ar] = av.y;
        As[(ac + 2) * 128 + ar] = av.z;
        As[(ac + 3) * 128 + ar] = av.w;
#pragma unroll
        for (int i = tid; i < 8 * OUT; i += 256)
            Bs[i] = W[(size_t)(k0 + i / OUT) * OUT + (i % OUT)];
        __syncthreads();
#pragma unroll
        for (int k = 0; k < 8; k++) {
            float a[RPT], b[8];
#pragma unroll
            for (int i = 0; i < RPT; i++) a[i] = As[k * 128 + ty * RPT + i];
            *(float4*)&b[0] = *(float4*)&Bs[k * OUT + tx * 8];
            *(float4*)&b[4] = *(float4*)&Bs[k * OUT + tx * 8 + 4];
#pragma unroll
            for (int i = 0; i < RPT; i++)
#pragma unroll
                for (int j = 0; j < 8; j++) acc[i][j] += a[i] * b[j];
        }
        __syncthreads();
    }

#pragma unroll
    for (int i = 0; i < RPT; i++) {
        int r = row0 + ty * RPT + i;
        if (r < n) {
            float sc = dinv[r];
            uint32_t h2[4];
#pragma unroll
            for (int j = 0; j < 4; j++) {
                __half2 hh = __floats2half2_rn(acc[i][j * 2] * sc,
                                               acc[i][j * 2 + 1] * sc);
                h2[j] = *(uint32_t*)&hh;
            }
            *(uint4*)&C[(size_t)r * OUT + tx * 8] = make_uint4(h2[0], h2[1], h2[2], h2[3]);
        }
    }
#endif
}

// ---------------------------------------------------------------------------
// init: zero cnt (whole grid) + parallel dtype probe (block 0) + cursor reset
// ---------------------------------------------------------------------------
__global__ void init_kernel(const int* __restrict__ w, int nwords,
                            int* cnt, int n) {
    int i = blockIdx.x * blockDim.x + threadIdx.x;
    if (i < n) cnt[i] = 0;
    if (blockIdx.x == 0) {
        __shared__ int sacc;
        if (threadIdx.x == 0) sacc = 0;
        __syncthreads();
        int limit = nwords < 2048 ? nwords : 2048;
        int acc = 0;
        for (int j = 2 * threadIdx.x + 1; j < limit; j += 512) acc |= w[j];
        if (acc) atomicOr(&sacc, 1);
        __syncthreads();
        if (threadIdx.x == 0) {
            g_idx64 = (sacc == 0) ? 1 : 0;
            g_cursor = 0;
        }
    }
}

__global__ void decode_hist_kernel(const int* __restrict__ w, int* cnt,
                                   int E, int n) {
    int e = blockIdx.x * blockDim.x + threadIdx.x;
    if (e >= E) return;
    int s, d;
    if (g_idx64) {
        s = w[2 * (size_t)e];
        d = w[2 * ((size_t)E + e)];
    } else {
        s = w[e];
        d = w[(size_t)E + e];
    }
    if ((unsigned)s >= (unsigned)n) s = 0;
    if ((unsigned)d >= (unsigned)n) d = 0;
    g_src[e] = s;
    g_dst[e] = d;
    g_rank[e] = atomicAdd(&cnt[d], 1);
}

// Order-free segment assignment + dinv.
__global__ void assign_kernel(const int* __restrict__ cnt, int* rowptr,
                              float* dinv, int n) {
    int i = blockIdx.x * blockDim.x + threadIdx.x;
    if (i >= n) return;
    int c = cnt[i];
    rowptr[i] = (c > 0) ? atomicAdd(&g_cursor, c) : 0;
    dinv[i] = rsqrtf(1.0f + (float)c);  // +1 self-loop
}

__global__ void scatter_sort_kernel(const int* __restrict__ src,
                                    const int* __restrict__ dst,
                                    const int* __restrict__ rank,
                                    const int* __restrict__ rowptr,
                                    int* sorted, int E) {
    int e = blockIdx.x * blockDim.x + threadIdx.x;
    if (e >= E) return;
    sorted[rowptr[dst[e]] + rank[e]] = src[e];
}

// ---------------------------------------------------------------------------
// Fused aggregate: res[d] = f( dinv[d] * (sum_in h[src] + h[d]) + bias )
// h fp16 (prescaled); fp32 accum; output fp16 (layer1) or fp32 (layer2/out).
// ---------------------------------------------------------------------------
__device__ __forceinline__ void ld4h(const __half* p, float* f) {
    uint2 u = *(const uint2*)p;
    float2 a = __half22float2(*(__half2*)&u.x);
    float2 b = __half22float2(*(__half2*)&u.y);
    f[0] = a.x; f[1] = a.y; f[2] = b.x; f[3] = b.y;
}
__device__ __forceinline__ void ld2h(const __half* p, float* f) {
    uint32_t u = *(const uint32_t*)p;
    float2 a = __half22float2(*(__half2*)&u);
    f[0] = a.x; f[1] = a.y;
}
__device__ __forceinline__ void st4(float* p, float4 v) { *(float4*)p = v; }
__device__ __forceinline__ void st4(__half* p, float4 v) {
    __half2 p0 = __floats2half2_rn(v.x, v.y);
    __half2 p1 = __floats2half2_rn(v.z, v.w);
    *(uint2*)p = make_uint2(*(uint32_t*)&p0, *(uint32_t*)&p1);
}
__device__ __forceinline__ void st2(float* p, float2 v) { *(float2*)p = v; }
__device__ __forceinline__ void st2(__half* p, float2 v) {
    __half2 p0 = __floats2half2_rn(v.x, v.y);
    *(uint32_t*)p = *(uint32_t*)&p0;
}

template <int DIM, bool RELU, typename OT>
__global__ void __launch_bounds__(256) aggregate_kernel(
    const int* __restrict__ rowptr, const int* __restrict__ cnt,
    const int* __restrict__ sorted,
    const __half* __restrict__ h, OT* __restrict__ res,
    const float* __restrict__ dinv, const float* __restrict__ bias, int n)
{
    constexpr int VPL = DIM / 32;  // halves per lane: 4 (D=128) or 2 (D=64)
    int node = (int)((blockIdx.x * (long long)blockDim.x + threadIdx.x) >> 5);
    int lane = threadIdx.x & 31;
    if (node >= n) return;

    const int beg = rowptr[node];
    const int end = beg + cnt[node];
    const int col = lane * VPL;

    float acc[VPL];
    if (VPL == 4) ld4h(&h[(size_t)node * DIM + col], acc);
    else          ld2h(&h[(size_t)node * DIM + col], acc);

    int e = beg;
    for (; e + 4 <= end; e += 4) {
        int s0 = sorted[e + 0], s1 = sorted[e + 1];
        int s2 = sorted[e + 2], s3 = sorted[e + 3];
        float v0[VPL], v1[VPL], v2[VPL], v3[VPL];
        if (VPL == 4) {
            ld4h(&h[(size_t)s0 * DIM + col], v0);
            ld4h(&h[(size_t)s1 * DIM + col], v1);
            ld4h(&h[(size_t)s2 * DIM + col], v2);
            ld4h(&h[(size_t)s3 * DIM + col], v3);
        } else {
            ld2h(&h[(size_t)s0 * DIM + col], v0);
            ld2h(&h[(size_t)s1 * DIM + col], v1);
            ld2h(&h[(size_t)s2 * DIM + col], v2);
            ld2h(&h[(size_t)s3 * DIM + col], v3);
        }
#pragma unroll
        for (int j = 0; j < VPL; j++)
            acc[j] += (v0[j] + v1[j]) + (v2[j] + v3[j]);
    }
    for (; e < end; e++) {
        int s = sorted[e];
        float v[VPL];
        if (VPL == 4) ld4h(&h[(size_t)s * DIM + col], v);
        else          ld2h(&h[(size_t)s * DIM + col], v);
#pragma unroll
        for (int j = 0; j < VPL; j++) acc[j] += v[j];
    }

    float di = dinv[node];
    if (VPL == 4) {
        float4 b = *(const float4*)&bias[col];
        float4 r;
        r.x = di * acc[0] + b.x;
        r.y = di * acc[1] + b.y;
        r.z = di * acc[2] + b.z;
        r.w = di * acc[3] + b.w;
        if (RELU) {
            r.x = fmaxf(r.x, 0.f); r.y = fmaxf(r.y, 0.f);
            r.z = fmaxf(r.z, 0.f); r.w = fmaxf(r.w, 0.f);
        }
        st4(&res[(size_t)node * DIM + col], r);
    } else {
        float2 b = *(const float2*)&bias[col];
        float2 r;
        r.x = di * acc[0] + b.x;
        r.y = di * acc[1] + b.y;
        if (RELU) { r.x = fmaxf(r.x, 0.f); r.y = fmaxf(r.y, 0.f); }
        st2(&res[(size_t)node * DIM + col], r);
    }
}

// ---------------------------------------------------------------------------
// launch
// ---------------------------------------------------------------------------
static inline int cdiv(long long a, long long b) { return (int)((a + b - 1) / b); }

extern "C" void kernel_launch(void* const* d_in, const int* in_sizes, int n_in,
                              void* d_out, int out_size)
{
    const float* x   = (const float*)d_in[0];
    const int*   eiw = (const int*)d_in[1];
    const float* W1  = (const float*)d_in[2];
    const float* b1  = (const float*)d_in[3];
    const float* W2  = (const float*)d_in[4];
    const float* b2  = (const float*)d_in[5];
    float*       out = (float*)d_out;

    const int n = in_sizes[0] / D0;
    int E = in_sizes[1] / 2;
    if (E > EMAX) E = EMAX;

    float* dinv;
    __half *h, *agg;
    int *srcp, *dstp, *rankp, *sorted, *cnt, *rowptr;
    cudaGetSymbolAddress((void**)&dinv,   g_dinv);
    cudaGetSymbolAddress((void**)&h,      g_h);
    cudaGetSymbolAddress((void**)&agg,    g_agg);
    cudaGetSymbolAddress((void**)&srcp,   g_src);
    cudaGetSymbolAddress((void**)&dstp,   g_dst);
    cudaGetSymbolAddress((void**)&rankp,  g_rank);
    cudaGetSymbolAddress((void**)&sorted, g_sorted);
    cudaGetSymbolAddress((void**)&cnt,    g_cnt);
    cudaGetSymbolAddress((void**)&rowptr, g_rowptr);

    constexpr int SMEM1 = 1024 + 2 * 128 * 256 + 2 * 128 * 256;
    constexpr int SMEM2 = 1024 + 2 * 128 * 256 + 2 * 64 * 256;
    cudaFuncSetAttribute(tc_gemm<128, float>,
                         cudaFuncAttributeMaxDynamicSharedMemorySize, SMEM1);
    cudaFuncSetAttribute(tc_gemm<64, __half>,
                         cudaFuncAttributeMaxDynamicSharedMemorySize, SMEM2);

    // --- CSR build ---
    init_kernel<<<cdiv(n, 256), 256>>>(eiw, in_sizes[1], cnt, n);
    decode_hist_kernel<<<cdiv(E, 256), 256>>>(eiw, cnt, E, n);
    assign_kernel<<<cdiv(n, 256), 256>>>(cnt, rowptr, dinv, n);
    scatter_sort_kernel<<<cdiv(E, 256), 256>>>(srcp, dstp, rankp, rowptr, sorted, E);

    // --- layer 1 ---
    tc_gemm<D1, float><<<cdiv(n, 128), 256, SMEM1>>>(x, W1, h, dinv, n);
    aggregate_kernel<D1, true, __half><<<cdiv(n, 8), 256>>>(
        rowptr, cnt, sorted, h, agg, dinv, b1, n);

    // --- layer 2 ---
    tc_gemm<D2, __half><<<cdiv(n, 128), 256, SMEM2>>>(agg, W2, h, dinv, n);
    aggregate_kernel<D2, false, float><<<cdiv(n, 8), 256>>>(
        rowptr, cnt, sorted, h, out, dinv, b2, n);
}